// round 1
// baseline (speedup 1.0000x reference)
#include <cuda_runtime.h>
#include <cuda_bf16.h>
#include <math.h>

// Problem constants
#define TT 4096   // B*S tokens
#define DD 1024   // d_model
#define FF 4096   // d_ff
#define EE 8      // experts
#define SS 2048   // seq
#define HH 16     // heads
#define DK 64     // head dim

// ---------------- scratch (device globals; no allocs allowed) ----------------
__device__ float g_q[TT * DD];
__device__ float g_k[TT * DD];
__device__ float g_v[TT * DD];
__device__ float g_ctx[TT * DD];
__device__ float g_res1[TT * DD];
__device__ float g_x1[TT * DD];
__device__ float g_act[2u * TT * FF];   // per-(token,slot) FFN hidden
__device__ float g_y[2u * TT * DD];     // per-(token,slot) expert output
__device__ float g_gatew[2 * TT];       // combine weights per (token,slot)
__device__ int   g_counts[EE];
__device__ int   g_list[EE * TT];       // entries = token*2 + slot

// ---------------- generic tiled SGEMM ----------------
// C[crow, n] = act( A[arow, :] @ W[e] + bias[e] ) (+ resid)
// arow/crow come from a per-expert gather list when provided.
#define BM 64
#define BN 64
#define BK 16

__global__ void gemm_kernel(
    const float* __restrict__ A,
    const float* __restrict__ Wbase,     // [E][K][N] (E=1 ok)
    const float* __restrict__ biasBase,  // [E][N] or null
    const float* __restrict__ resid,     // [rows][N] or null (indexed by crow)
    float* __restrict__ C,
    int M, int K, int N,
    int lda, int ldc,
    const int* __restrict__ listBase,    // per-expert list (stride TT) or null
    const int* __restrict__ counts,      // per-expert counts or null
    int a_shift,                         // list entry >> a_shift = A row
    int actmode)                         // 0 none, 1 gelu, 2 silu, 3 by-expert-parity
{
    int e = blockIdx.z;
    const float* W = Wbase + (size_t)e * K * N;
    const float* bias = biasBase ? biasBase + (size_t)e * N : nullptr;
    const int* list = listBase ? listBase + e * TT : nullptr;
    int Me = counts ? counts[e] : M;
    int m0 = blockIdx.y * BM;
    if (m0 >= Me) return;
    int n0 = blockIdx.x * BN;

    __shared__ float As[BK][BM];
    __shared__ float Bs[BK][BN];

    int tid = threadIdx.x;
    int tx = tid & 15, ty = tid >> 4;

    float acc[4][4] = {};

    int a_rows[4];
#pragma unroll
    for (int i = 0; i < 4; i++) {
        int m = m0 + (tid >> 4) + i * 16;
        int row = -1;
        if (m < Me) row = list ? (list[m] >> a_shift) : m;
        a_rows[i] = row;
    }

    for (int k0 = 0; k0 < K; k0 += BK) {
#pragma unroll
        for (int i = 0; i < 4; i++) {
            int ml = (tid >> 4) + i * 16;
            int kk = tid & 15;
            float vv = 0.f;
            if (a_rows[i] >= 0) vv = A[(size_t)a_rows[i] * lda + k0 + kk];
            As[kk][ml] = vv;
        }
#pragma unroll
        for (int i = 0; i < 4; i++) {
            int kk = (tid >> 6) + i * 4;
            int nn = tid & 63;
            Bs[kk][nn] = W[(size_t)(k0 + kk) * N + n0 + nn];
        }
        __syncthreads();
#pragma unroll
        for (int kk = 0; kk < BK; kk++) {
            float4 a4 = *(const float4*)&As[kk][ty * 4];
            float4 b4 = *(const float4*)&Bs[kk][tx * 4];
            float av[4] = {a4.x, a4.y, a4.z, a4.w};
            float bv[4] = {b4.x, b4.y, b4.z, b4.w};
#pragma unroll
            for (int i = 0; i < 4; i++)
#pragma unroll
                for (int j = 0; j < 4; j++)
                    acc[i][j] += av[i] * bv[j];
        }
        __syncthreads();
    }

    int act = (actmode == 3) ? ((e & 1) ? 2 : 1) : actmode;
#pragma unroll
    for (int i = 0; i < 4; i++) {
        int m = m0 + ty * 4 + i;
        if (m >= Me) continue;
        int crow = list ? list[m] : m;
        float4 r4 = make_float4(0.f, 0.f, 0.f, 0.f);
        if (resid) r4 = *(const float4*)&resid[(size_t)crow * ldc + n0 + tx * 4];
        float o[4];
#pragma unroll
        for (int j = 0; j < 4; j++) {
            int n = n0 + tx * 4 + j;
            float vv = acc[i][j];
            if (bias) vv += bias[n];
            o[j] = vv;
        }
        o[0] += r4.x; o[1] += r4.y; o[2] += r4.z; o[3] += r4.w;
        if (act == 1) {
#pragma unroll
            for (int j = 0; j < 4; j++)
                o[j] = 0.5f * o[j] * (1.f + erff(o[j] * 0.70710678118654752f));
        } else if (act == 2) {
#pragma unroll
            for (int j = 0; j < 4; j++)
                o[j] = o[j] / (1.f + __expf(-o[j]));
        }
        *(float4*)&C[(size_t)crow * ldc + n0 + tx * 4] =
            make_float4(o[0], o[1], o[2], o[3]);
    }
}

// ---------------- flash attention: grid (S/64, H, B), block 256 ----------------
__global__ void attn_kernel(const float* __restrict__ q,
                            const float* __restrict__ k,
                            const float* __restrict__ v,
                            float* __restrict__ ctx)
{
    int qt = blockIdx.x, h = blockIdx.y, b = blockIdx.z;
    int tid = threadIdx.x;
    int tx = tid & 15, ty = tid >> 4;

    __shared__ float Qt[64][64];   // [dk][q]
    __shared__ float Ks[32][65];   // [key][dk], pad 1
    __shared__ float Vs[32][64];   // [key][dk]
    __shared__ float Ps[64][33];   // [q][key], pad 1

    size_t base = ((size_t)b * SS) * DD + (size_t)h * DK;
    const float* qb = q + base + (size_t)qt * 64 * DD;
    const float* kb = k + base;
    const float* vb = v + base;

#pragma unroll
    for (int i = 0; i < 16; i++) {
        int idx = tid + i * 256;
        int row = idx >> 6, col = idx & 63;
        Qt[col][row] = qb[(size_t)row * DD + col];
    }
    __syncthreads();

    float acc[4][4] = {};
    float mrow[4], lrow[4];
#pragma unroll
    for (int i = 0; i < 4; i++) { mrow[i] = -1e30f; lrow[i] = 0.f; }
    const float scale = 0.125f;  // 1/sqrt(64)

    for (int k0 = 0; k0 < SS; k0 += 32) {
#pragma unroll
        for (int i = 0; i < 8; i++) {
            int idx = tid + i * 256;
            int row = idx >> 6, col = idx & 63;
            Ks[row][col] = kb[(size_t)(k0 + row) * DD + col];
            Vs[row][col] = vb[(size_t)(k0 + row) * DD + col];
        }
        __syncthreads();

        float s[4][2] = {};
#pragma unroll
        for (int kk = 0; kk < 64; kk++) {
            float4 q4 = *(const float4*)&Qt[kk][ty * 4];
            float k0v = Ks[tx * 2][kk];
            float k1v = Ks[tx * 2 + 1][kk];
            s[0][0] += q4.x * k0v; s[0][1] += q4.x * k1v;
            s[1][0] += q4.y * k0v; s[1][1] += q4.y * k1v;
            s[2][0] += q4.z * k0v; s[2][1] += q4.z * k1v;
            s[3][0] += q4.w * k0v; s[3][1] += q4.w * k1v;
        }
#pragma unroll
        for (int i = 0; i < 4; i++) { s[i][0] *= scale; s[i][1] *= scale; }

#pragma unroll
        for (int i = 0; i < 4; i++) {
            float rm = fmaxf(s[i][0], s[i][1]);
#pragma unroll
            for (int o = 1; o < 16; o <<= 1)
                rm = fmaxf(rm, __shfl_xor_sync(0xffffffffu, rm, o));
            float mnew = fmaxf(mrow[i], rm);
            float corr = __expf(mrow[i] - mnew);
            float p0 = __expf(s[i][0] - mnew);
            float p1 = __expf(s[i][1] - mnew);
            float rs = p0 + p1;
#pragma unroll
            for (int o = 1; o < 16; o <<= 1)
                rs += __shfl_xor_sync(0xffffffffu, rs, o);
            lrow[i] = lrow[i] * corr + rs;
            mrow[i] = mnew;
#pragma unroll
            for (int j = 0; j < 4; j++) acc[i][j] *= corr;
            Ps[ty * 4 + i][tx * 2] = p0;
            Ps[ty * 4 + i][tx * 2 + 1] = p1;
        }
        __syncthreads();

#pragma unroll
        for (int kk = 0; kk < 32; kk++) {
            float4 v4 = *(const float4*)&Vs[kk][tx * 4];
            float p[4];
#pragma unroll
            for (int i = 0; i < 4; i++) p[i] = Ps[ty * 4 + i][kk];
#pragma unroll
            for (int i = 0; i < 4; i++) {
                acc[i][0] += p[i] * v4.x;
                acc[i][1] += p[i] * v4.y;
                acc[i][2] += p[i] * v4.z;
                acc[i][3] += p[i] * v4.w;
            }
        }
        __syncthreads();
    }

    float* cb = ctx + base + (size_t)qt * 64 * DD;
#pragma unroll
    for (int i = 0; i < 4; i++) {
        float inv = 1.f / lrow[i];
        int qrow = ty * 4 + i;
        *(float4*)&cb[(size_t)qrow * DD + tx * 4] =
            make_float4(acc[i][0] * inv, acc[i][1] * inv,
                        acc[i][2] * inv, acc[i][3] * inv);
    }
}

// ---------------- layernorm ----------------
__global__ void ln_kernel(const float* __restrict__ in,
                          const float* __restrict__ gam,
                          const float* __restrict__ bet,
                          float* __restrict__ out)
{
    __shared__ float ssum[8], ssum2[8];
    __shared__ float smean, srstd;
    int t = blockIdx.x;
    const float4* r = (const float4*)(in + (size_t)t * DD);
    float4 vv = r[threadIdx.x];
    float s = vv.x + vv.y + vv.z + vv.w;
    float s2 = vv.x * vv.x + vv.y * vv.y + vv.z * vv.z + vv.w * vv.w;
    int lane = threadIdx.x & 31, w = threadIdx.x >> 5;
#pragma unroll
    for (int o = 16; o; o >>= 1) {
        s += __shfl_xor_sync(~0u, s, o);
        s2 += __shfl_xor_sync(~0u, s2, o);
    }
    if (!lane) { ssum[w] = s; ssum2[w] = s2; }
    __syncthreads();
    if (threadIdx.x == 0) {
        float a = 0.f, bb = 0.f;
#pragma unroll
        for (int i = 0; i < 8; i++) { a += ssum[i]; bb += ssum2[i]; }
        float mean = a * (1.f / DD);
        float var = bb * (1.f / DD) - mean * mean;
        smean = mean; srstd = rsqrtf(var + 1e-5f);
    }
    __syncthreads();
    float4 g4 = ((const float4*)gam)[threadIdx.x];
    float4 b4 = ((const float4*)bet)[threadIdx.x];
    float m = smean, rs = srstd;
    float4 o4;
    o4.x = (vv.x - m) * rs * g4.x + b4.x;
    o4.y = (vv.y - m) * rs * g4.y + b4.y;
    o4.z = (vv.z - m) * rs * g4.z + b4.z;
    o4.w = (vv.w - m) * rs * g4.w + b4.w;
    ((float4*)(out + (size_t)t * DD))[threadIdx.x] = o4;
}

// ---------------- gate: logits, top-2 softmax, dispatch ----------------
__global__ void zero_counts_kernel() {
    if (threadIdx.x < EE) g_counts[threadIdx.x] = 0;
}

__global__ void gate_kernel(const float* __restrict__ x1,
                            const float* __restrict__ gw,   // [D, E]
                            const float* __restrict__ gb)
{
    int t = blockIdx.x * (blockDim.x / 32) + (threadIdx.x >> 5);
    int lane = threadIdx.x & 31;
    float acc[EE] = {};
    const float* xr = x1 + (size_t)t * DD;
    for (int d = lane; d < DD; d += 32) {
        float xv = xr[d];
        const float* grow = gw + (size_t)d * EE;
#pragma unroll
        for (int e = 0; e < EE; e++) acc[e] += xv * grow[e];
    }
#pragma unroll
    for (int e = 0; e < EE; e++)
#pragma unroll
        for (int o = 16; o; o >>= 1) acc[e] += __shfl_xor_sync(~0u, acc[e], o);
    if (lane == 0) {
#pragma unroll
        for (int e = 0; e < EE; e++) acc[e] += gb[e];
        float best = -1e30f; int bi = 0;
#pragma unroll
        for (int e = 0; e < EE; e++)
            if (acc[e] > best) { best = acc[e]; bi = e; }
        float best2 = -1e30f; int bi2 = 0;
#pragma unroll
        for (int e = 0; e < EE; e++)
            if (e != bi && acc[e] > best2) { best2 = acc[e]; bi2 = e; }
        float w0 = 1.f / (1.f + __expf(best2 - best));
        g_gatew[2 * t] = w0;
        g_gatew[2 * t + 1] = 1.f - w0;
        int p0 = atomicAdd(&g_counts[bi], 1);
        g_list[bi * TT + p0] = 2 * t;
        int p1 = atomicAdd(&g_counts[bi2], 1);
        g_list[bi2 * TT + p1] = 2 * t + 1;
    }
}

// ---------------- combine experts + residual + LN3 -> out ----------------
__global__ void combine_ln_kernel(const float* __restrict__ x1,
                                  const float* __restrict__ gam,
                                  const float* __restrict__ bet,
                                  float* __restrict__ out)
{
    __shared__ float ssum[8], ssum2[8];
    __shared__ float smean, srstd;
    int t = blockIdx.x;
    float w0 = g_gatew[2 * t], w1 = g_gatew[2 * t + 1];
    const float4* xr = (const float4*)(x1 + (size_t)t * DD);
    const float4* y0 = (const float4*)(g_y + (size_t)(2 * t) * DD);
    const float4* y1 = (const float4*)(g_y + (size_t)(2 * t + 1) * DD);
    float4 a = xr[threadIdx.x];
    float4 c0 = y0[threadIdx.x];
    float4 c1 = y1[threadIdx.x];
    float4 vv;
    vv.x = a.x + w0 * c0.x + w1 * c1.x;
    vv.y = a.y + w0 * c0.y + w1 * c1.y;
    vv.z = a.z + w0 * c0.z + w1 * c1.z;
    vv.w = a.w + w0 * c0.w + w1 * c1.w;
    float s = vv.x + vv.y + vv.z + vv.w;
    float s2 = vv.x * vv.x + vv.y * vv.y + vv.z * vv.z + vv.w * vv.w;
    int lane = threadIdx.x & 31, w = threadIdx.x >> 5;
#pragma unroll
    for (int o = 16; o; o >>= 1) {
        s += __shfl_xor_sync(~0u, s, o);
        s2 += __shfl_xor_sync(~0u, s2, o);
    }
    if (!lane) { ssum[w] = s; ssum2[w] = s2; }
    __syncthreads();
    if (threadIdx.x == 0) {
        float aa = 0.f, bb = 0.f;
#pragma unroll
        for (int i = 0; i < 8; i++) { aa += ssum[i]; bb += ssum2[i]; }
        float mean = aa * (1.f / DD);
        float var = bb * (1.f / DD) - mean * mean;
        smean = mean; srstd = rsqrtf(var + 1e-5f);
    }
    __syncthreads();
    float4 g4 = ((const float4*)gam)[threadIdx.x];
    float4 b4 = ((const float4*)bet)[threadIdx.x];
    float m = smean, rs = srstd;
    float4 o4;
    o4.x = (vv.x - m) * rs * g4.x + b4.x;
    o4.y = (vv.y - m) * rs * g4.y + b4.y;
    o4.z = (vv.z - m) * rs * g4.z + b4.z;
    o4.w = (vv.w - m) * rs * g4.w + b4.w;
    ((float4*)(out + (size_t)t * DD))[threadIdx.x] = o4;
}

// ---------------- launch ----------------
extern "C" void kernel_launch(void* const* d_in, const int* in_sizes, int n_in,
                              void* d_out, int out_size)
{
    const float* x    = (const float*)d_in[0];
    const float* Wq   = (const float*)d_in[1];
    const float* bq   = (const float*)d_in[2];
    const float* Wk   = (const float*)d_in[3];
    const float* bk   = (const float*)d_in[4];
    const float* Wv   = (const float*)d_in[5];
    const float* bv   = (const float*)d_in[6];
    const float* Wo   = (const float*)d_in[7];
    const float* bo   = (const float*)d_in[8];
    const float* ln1g = (const float*)d_in[9];
    const float* ln1b = (const float*)d_in[10];
    const float* gw   = (const float*)d_in[11];
    const float* gb   = (const float*)d_in[12];
    const float* W1   = (const float*)d_in[13];
    const float* b1   = (const float*)d_in[14];
    const float* W2   = (const float*)d_in[15];
    const float* b2   = (const float*)d_in[16];
    const float* ln3g = (const float*)d_in[17];
    const float* ln3b = (const float*)d_in[18];
    float* out = (float*)d_out;

    float *pq, *pk, *pv, *pctx, *pres1, *px1, *pact, *py, *pgatew;
    int *pcounts, *plist;
    cudaGetSymbolAddress((void**)&pq, g_q);
    cudaGetSymbolAddress((void**)&pk, g_k);
    cudaGetSymbolAddress((void**)&pv, g_v);
    cudaGetSymbolAddress((void**)&pctx, g_ctx);
    cudaGetSymbolAddress((void**)&pres1, g_res1);
    cudaGetSymbolAddress((void**)&px1, g_x1);
    cudaGetSymbolAddress((void**)&pact, g_act);
    cudaGetSymbolAddress((void**)&py, g_y);
    cudaGetSymbolAddress((void**)&pgatew, g_gatew);
    cudaGetSymbolAddress((void**)&pcounts, g_counts);
    cudaGetSymbolAddress((void**)&plist, g_list);

    dim3 blk(256);

    // QKV projections
    dim3 gqkv(DD / BN, TT / BM, 1);
    gemm_kernel<<<gqkv, blk>>>(x, Wq, bq, nullptr, pq, TT, DD, DD, DD, DD,
                               nullptr, nullptr, 0, 0);
    gemm_kernel<<<gqkv, blk>>>(x, Wk, bk, nullptr, pk, TT, DD, DD, DD, DD,
                               nullptr, nullptr, 0, 0);
    gemm_kernel<<<gqkv, blk>>>(x, Wv, bv, nullptr, pv, TT, DD, DD, DD, DD,
                               nullptr, nullptr, 0, 0);

    // attention
    dim3 gattn(SS / 64, HH, 2);
    attn_kernel<<<gattn, blk>>>(pq, pk, pv, pctx);

    // O projection + residual add (resid = x)
    gemm_kernel<<<gqkv, blk>>>(pctx, Wo, bo, x, pres1, TT, DD, DD, DD, DD,
                               nullptr, nullptr, 0, 0);

    // LN1
    ln_kernel<<<TT, blk>>>(pres1, ln1g, ln1b, px1);

    // gate + dispatch
    zero_counts_kernel<<<1, 32>>>();
    gate_kernel<<<TT / 8, blk>>>(px1, gw, gb);

    // FFN1 (gathered): h = act(x1[token] @ W1[e] + b1[e]) -> g_act[entry]
    dim3 gffn1(FF / BN, TT / BM, EE);
    gemm_kernel<<<gffn1, blk>>>(px1, W1, b1, nullptr, pact, TT, DD, FF, DD, FF,
                                plist, pcounts, 1, 3);

    // FFN2 (gathered): y = g_act[entry] @ W2[e] + b2[e] -> g_y[entry]
    dim3 gffn2(DD / BN, TT / BM, EE);
    gemm_kernel<<<gffn2, blk>>>(pact, W2, b2, nullptr, py, TT, FF, DD, FF, DD,
                                plist, pcounts, 0, 0);

    // combine + residual + LN3 -> out
    combine_ln_kernel<<<TT, blk>>>(px1, ln3g, ln3b, out);
}

// round 3
// speedup vs baseline: 2.2215x; 2.2215x over previous
#include <cuda_runtime.h>
#include <cuda_bf16.h>
#include <math.h>
#include <stdint.h>

// Problem constants
#define TT 4096   // B*S tokens
#define DD 1024   // d_model
#define FF 4096   // d_ff
#define EE 8      // experts
#define SS 2048   // seq
#define HH 16     // heads
#define DK 64     // head dim

// ---------------- scratch (device globals; no allocs allowed) ----------------
__device__ float g_qkv[3u * TT * DD];
__device__ float g_ctx[TT * DD];
__device__ float g_res1[TT * DD];
__device__ float g_x1[TT * DD];
__device__ float g_act[2u * TT * FF];
__device__ float g_y[2u * TT * DD];
__device__ float g_gatew[2 * TT];
__device__ int   g_counts[EE];
__device__ int   g_list[EE * TT];
__device__ float g_w1T[(size_t)EE * DD * FF];   // [E][F][D]
__device__ float g_w2T[(size_t)EE * FF * DD];   // [E][D][F]

// ================= FFMA fp32 GEMM (exact; used for QKV + O to keep x1
// bit-stable so the MoE gate never flips vs the fp32 reference path) =========
#define BM 64
#define BN 64
#define BK 16

__global__ void gemm_kernel(
    const float* __restrict__ A,
    const float* __restrict__ Wbase,     // [K][N]
    const float* __restrict__ bias,
    const float* __restrict__ resid,
    float* __restrict__ C,
    int M, int K, int N)
{
    const float* W = Wbase;
    int m0 = blockIdx.y * BM;
    int n0 = blockIdx.x * BN;

    __shared__ float As[BK][BM];
    __shared__ float Bs[BK][BN];

    int tid = threadIdx.x;
    int tx = tid & 15, ty = tid >> 4;

    float acc[4][4] = {};

    for (int k0 = 0; k0 < K; k0 += BK) {
#pragma unroll
        for (int i = 0; i < 4; i++) {
            int ml = (tid >> 4) + i * 16;
            int kk = tid & 15;
            As[kk][ml] = A[(size_t)(m0 + ml) * K + k0 + kk];
        }
#pragma unroll
        for (int i = 0; i < 4; i++) {
            int kk = (tid >> 6) + i * 4;
            int nn = tid & 63;
            Bs[kk][nn] = W[(size_t)(k0 + kk) * N + n0 + nn];
        }
        __syncthreads();
#pragma unroll
        for (int kk = 0; kk < BK; kk++) {
            float4 a4 = *(const float4*)&As[kk][ty * 4];
            float4 b4 = *(const float4*)&Bs[kk][tx * 4];
            float av[4] = {a4.x, a4.y, a4.z, a4.w};
            float bv[4] = {b4.x, b4.y, b4.z, b4.w};
#pragma unroll
            for (int i = 0; i < 4; i++)
#pragma unroll
                for (int j = 0; j < 4; j++)
                    acc[i][j] += av[i] * bv[j];
        }
        __syncthreads();
    }

#pragma unroll
    for (int i = 0; i < 4; i++) {
        int m = m0 + ty * 4 + i;
        float4 r4 = make_float4(0.f, 0.f, 0.f, 0.f);
        if (resid) r4 = *(const float4*)&resid[(size_t)m * N + n0 + tx * 4];
        float o[4];
#pragma unroll
        for (int j = 0; j < 4; j++) {
            int n = n0 + tx * 4 + j;
            o[j] = acc[i][j] + (bias ? bias[n] : 0.f);
        }
        o[0] += r4.x; o[1] += r4.y; o[2] += r4.z; o[3] += r4.w;
        *(float4*)&C[(size_t)m * N + n0 + tx * 4] =
            make_float4(o[0], o[1], o[2], o[3]);
    }
}

// ================= tf32 mma.sync GEMM for the MoE FFN =======================
// Tile 128x128x32, 256 threads (8 warps: 4 over M x 2 over N), cp.async
// double buffering. A rows gathered through the expert dispatch list.
#define LDP 36                       // padded floats per smem row (bank-safe)
#define TILE_F (128 * LDP)           // floats per (A or B) stage
#define MMA_SMEM_BYTES (4 * TILE_F * 4 * 2 / 2)  // 2 stages * (A+B) = 73728
// explicit: 2 stages * 2 tiles * 128*36 floats * 4B = 73728
#define MMA_SMEM (2 * 2 * TILE_F * 4)

__device__ __forceinline__ uint32_t smem_u32(const void* p) {
    uint32_t a;
    asm("{ .reg .u64 t; cvta.to.shared.u64 t, %1; cvt.u32.u64 %0, t; }" : "=r"(a) : "l"(p));
    return a;
}
__device__ __forceinline__ void cp16(uint32_t dst, const void* src) {
    asm volatile("cp.async.cg.shared.global [%0], [%1], 16;" :: "r"(dst), "l"(src));
}
__device__ __forceinline__ void cp16z(uint32_t dst, const void* src, int sz) {
    asm volatile("cp.async.cg.shared.global [%0], [%1], 16, %2;" :: "r"(dst), "l"(src), "r"(sz));
}
__device__ __forceinline__ void cp_commit() {
    asm volatile("cp.async.commit_group;");
}
__device__ __forceinline__ void cp_wait1() {
    asm volatile("cp.async.wait_group 1;" ::: "memory");
}
__device__ __forceinline__ void cp_wait0() {
    asm volatile("cp.async.wait_group 0;" ::: "memory");
}
__device__ __forceinline__ void mma_tf32(float* d, const float* a, const float* b) {
    asm volatile(
        "mma.sync.aligned.m16n8k8.row.col.f32.tf32.tf32.f32 "
        "{%0,%1,%2,%3}, {%4,%5,%6,%7}, {%8,%9}, {%0,%1,%2,%3};"
        : "+f"(d[0]), "+f"(d[1]), "+f"(d[2]), "+f"(d[3])
        : "r"(__float_as_uint(a[0])), "r"(__float_as_uint(a[1])),
          "r"(__float_as_uint(a[2])), "r"(__float_as_uint(a[3])),
          "r"(__float_as_uint(b[0])), "r"(__float_as_uint(b[1])));
}

__global__ void __launch_bounds__(256)
mm_mma_kernel(const float* __restrict__ A,
              const float* __restrict__ WT,        // [E][N][K] (k-major rows)
              const float* __restrict__ biasBase,  // [E][N]
              float* __restrict__ C,
              int M, int K, int N, int lda, int ldc,
              const int* __restrict__ listBase, const int* __restrict__ counts,
              int a_shift, int actmode)
{
    int e = blockIdx.z;
    const int* list = listBase + e * TT;
    int Me = counts[e];
    int m0 = blockIdx.y * 128;
    if (m0 >= Me) return;
    int n0 = blockIdx.x * 128;
    const float* W = WT + (size_t)e * N * K;
    const float* bias = biasBase + (size_t)e * N;

    extern __shared__ float smf[];
    float* As = smf;                    // [2][128][LDP]
    float* Bs = smf + 2 * TILE_F;       // [2][128][LDP]
    uint32_t uA = smem_u32(As);
    uint32_t uB = smem_u32(Bs);

    __shared__ int rows_s[128];
    __shared__ int crows_s[128];

    int tid = threadIdx.x;
    if (tid < 128) {
        int m = m0 + tid;
        int r = -1, cr = -1;
        if (m < Me) { int ent = list[m]; r = ent >> a_shift; cr = ent; }
        rows_s[tid] = r; crows_s[tid] = cr;
    }
    __syncthreads();

    // copy one 128x32 stage of A (gathered) and B
    auto load_stage = [&](int s, int k0) {
#pragma unroll
        for (int i = 0; i < 4; i++) {
            int chunk = tid + i * 256;       // 0..1023
            int row = chunk >> 3;
            int kc = chunk & 7;
            uint32_t off = (uint32_t)(s * TILE_F + row * LDP + kc * 4) * 4u;
            int ar = rows_s[row];
            const float* srcA = (ar >= 0) ? A + (size_t)ar * lda + k0 + kc * 4 : A;
            cp16z(uA + off, srcA, (ar >= 0) ? 16 : 0);
            const float* srcB = W + (size_t)(n0 + row) * K + k0 + kc * 4;
            cp16(uB + off, srcB);
        }
    };

    int NC = K >> 5;
    load_stage(0, 0); cp_commit();
    load_stage(1, 32); cp_commit();

    int w = tid >> 5, lane = tid & 31;
    int wm = w & 3, wn = w >> 2;
    int g = lane >> 2, ct = lane & 3;

    float acc[2][8][4];
#pragma unroll
    for (int mi = 0; mi < 2; mi++)
#pragma unroll
        for (int ni = 0; ni < 8; ni++)
#pragma unroll
            for (int j = 0; j < 4; j++) acc[mi][ni][j] = 0.f;

    for (int i = 0; i < NC; i++) {
        if (i + 1 < NC) cp_wait1(); else cp_wait0();
        __syncthreads();
        const float* Aw = As + (i & 1) * TILE_F;
        const float* Bw = Bs + (i & 1) * TILE_F;
#pragma unroll
        for (int ks = 0; ks < 4; ks++) {
            int kc = ks * 8 + ct;
            float afr[2][4];
#pragma unroll
            for (int mi = 0; mi < 2; mi++) {
                int rb = wm * 32 + mi * 16;
                afr[mi][0] = Aw[(rb + g) * LDP + kc];
                afr[mi][1] = Aw[(rb + g + 8) * LDP + kc];
                afr[mi][2] = Aw[(rb + g) * LDP + kc + 4];
                afr[mi][3] = Aw[(rb + g + 8) * LDP + kc + 4];
            }
            float bfr[8][2];
#pragma unroll
            for (int ni = 0; ni < 8; ni++) {
                int nb = wn * 64 + ni * 8;
                bfr[ni][0] = Bw[(nb + g) * LDP + kc];
                bfr[ni][1] = Bw[(nb + g) * LDP + kc + 4];
            }
#pragma unroll
            for (int mi = 0; mi < 2; mi++)
#pragma unroll
                for (int ni = 0; ni < 8; ni++)
                    mma_tf32(acc[mi][ni], afr[mi], bfr[ni]);
        }
        __syncthreads();
        if (i + 2 < NC) { load_stage(i & 1, (i + 2) << 5); cp_commit(); }
    }

    // epilogue: bias + activation, scatter to C rows
    int act = (actmode == 3) ? ((e & 1) ? 2 : 1) : actmode;
#pragma unroll
    for (int mi = 0; mi < 2; mi++) {
#pragma unroll
        for (int h = 0; h < 2; h++) {
            int rl = wm * 32 + mi * 16 + g + h * 8;
            int crow = crows_s[rl];
            if (crow < 0) continue;
            float* Crow = C + (size_t)crow * ldc;
#pragma unroll
            for (int ni = 0; ni < 8; ni++) {
                int col = n0 + wn * 64 + ni * 8 + 2 * ct;
                float v0 = acc[mi][ni][2 * h + 0] + bias[col];
                float v1 = acc[mi][ni][2 * h + 1] + bias[col + 1];
                if (act == 1) {
                    v0 = 0.5f * v0 * (1.f + erff(v0 * 0.70710678118654752f));
                    v1 = 0.5f * v1 * (1.f + erff(v1 * 0.70710678118654752f));
                } else if (act == 2) {
                    v0 = v0 / (1.f + __expf(-v0));
                    v1 = v1 / (1.f + __expf(-v1));
                }
                *(float2*)&Crow[col] = make_float2(v0, v1);
            }
        }
    }
}

// ---------------- transpose [R][C] -> [C][R] (per z slice) ----------------
__global__ void transpose_kernel(const float* __restrict__ in, float* __restrict__ out,
                                 int R, int C)
{
    __shared__ float t[32][33];
    const float* ip = in + (size_t)blockIdx.z * R * C;
    float* op = out + (size_t)blockIdx.z * R * C;
    int x = blockIdx.x * 32 + threadIdx.x;
    int y = blockIdx.y * 32 + threadIdx.y;
#pragma unroll
    for (int i = 0; i < 4; i++)
        t[threadIdx.y + i * 8][threadIdx.x] = ip[(size_t)(y + i * 8) * C + x];
    __syncthreads();
    int x2 = blockIdx.y * 32 + threadIdx.x;
    int y2 = blockIdx.x * 32 + threadIdx.y;
#pragma unroll
    for (int i = 0; i < 4; i++)
        op[(size_t)(y2 + i * 8) * R + x2] = t[threadIdx.x][threadIdx.y + i * 8];
}

// ---------------- flash attention (fp32) ----------------
__global__ void attn_kernel(const float* __restrict__ q,
                            const float* __restrict__ k,
                            const float* __restrict__ v,
                            float* __restrict__ ctx)
{
    int qt = blockIdx.x, h = blockIdx.y, b = blockIdx.z;
    int tid = threadIdx.x;
    int tx = tid & 15, ty = tid >> 4;

    __shared__ float Qt[64][64];
    __shared__ float Ks[32][65];
    __shared__ float Vs[32][64];
    __shared__ float Ps[64][33];

    size_t base = ((size_t)b * SS) * DD + (size_t)h * DK;
    const float* qb = q + base + (size_t)qt * 64 * DD;
    const float* kb = k + base;
    const float* vb = v + base;

#pragma unroll
    for (int i = 0; i < 16; i++) {
        int idx = tid + i * 256;
        int row = idx >> 6, col = idx & 63;
        Qt[col][row] = qb[(size_t)row * DD + col];
    }
    __syncthreads();

    float acc[4][4] = {};
    float mrow[4], lrow[4];
#pragma unroll
    for (int i = 0; i < 4; i++) { mrow[i] = -1e30f; lrow[i] = 0.f; }
    const float scale = 0.125f;

    for (int k0 = 0; k0 < SS; k0 += 32) {
#pragma unroll
        for (int i = 0; i < 8; i++) {
            int idx = tid + i * 256;
            int row = idx >> 6, col = idx & 63;
            Ks[row][col] = kb[(size_t)(k0 + row) * DD + col];
            Vs[row][col] = vb[(size_t)(k0 + row) * DD + col];
        }
        __syncthreads();

        float s[4][2] = {};
#pragma unroll
        for (int kk = 0; kk < 64; kk++) {
            float4 q4 = *(const float4*)&Qt[kk][ty * 4];
            float k0v = Ks[tx * 2][kk];
            float k1v = Ks[tx * 2 + 1][kk];
            s[0][0] += q4.x * k0v; s[0][1] += q4.x * k1v;
            s[1][0] += q4.y * k0v; s[1][1] += q4.y * k1v;
            s[2][0] += q4.z * k0v; s[2][1] += q4.z * k1v;
            s[3][0] += q4.w * k0v; s[3][1] += q4.w * k1v;
        }
#pragma unroll
        for (int i = 0; i < 4; i++) { s[i][0] *= scale; s[i][1] *= scale; }

#pragma unroll
        for (int i = 0; i < 4; i++) {
            float rm = fmaxf(s[i][0], s[i][1]);
#pragma unroll
            for (int o = 1; o < 16; o <<= 1)
                rm = fmaxf(rm, __shfl_xor_sync(0xffffffffu, rm, o));
            float mnew = fmaxf(mrow[i], rm);
            float corr = __expf(mrow[i] - mnew);
            float p0 = __expf(s[i][0] - mnew);
            float p1 = __expf(s[i][1] - mnew);
            float rs = p0 + p1;
#pragma unroll
            for (int o = 1; o < 16; o <<= 1)
                rs += __shfl_xor_sync(0xffffffffu, rs, o);
            lrow[i] = lrow[i] * corr + rs;
            mrow[i] = mnew;
#pragma unroll
            for (int j = 0; j < 4; j++) acc[i][j] *= corr;
            Ps[ty * 4 + i][tx * 2] = p0;
            Ps[ty * 4 + i][tx * 2 + 1] = p1;
        }
        __syncthreads();

#pragma unroll
        for (int kk = 0; kk < 32; kk++) {
            float4 v4 = *(const float4*)&Vs[kk][tx * 4];
            float p[4];
#pragma unroll
            for (int i = 0; i < 4; i++) p[i] = Ps[ty * 4 + i][kk];
#pragma unroll
            for (int i = 0; i < 4; i++) {
                acc[i][0] += p[i] * v4.x;
                acc[i][1] += p[i] * v4.y;
                acc[i][2] += p[i] * v4.z;
                acc[i][3] += p[i] * v4.w;
            }
        }
        __syncthreads();
    }

    float* cb = ctx + base + (size_t)qt * 64 * DD;
#pragma unroll
    for (int i = 0; i < 4; i++) {
        float inv = 1.f / lrow[i];
        int qrow = ty * 4 + i;
        *(float4*)&cb[(size_t)qrow * DD + tx * 4] =
            make_float4(acc[i][0] * inv, acc[i][1] * inv,
                        acc[i][2] * inv, acc[i][3] * inv);
    }
}

// ---------------- layernorm ----------------
__global__ void ln_kernel(const float* __restrict__ in,
                          const float* __restrict__ gam,
                          const float* __restrict__ bet,
                          float* __restrict__ out)
{
    __shared__ float ssum[8], ssum2[8];
    __shared__ float smean, srstd;
    int t = blockIdx.x;
    const float4* r = (const float4*)(in + (size_t)t * DD);
    float4 vv = r[threadIdx.x];
    float s = vv.x + vv.y + vv.z + vv.w;
    float s2 = vv.x * vv.x + vv.y * vv.y + vv.z * vv.z + vv.w * vv.w;
    int lane = threadIdx.x & 31, w = threadIdx.x >> 5;
#pragma unroll
    for (int o = 16; o; o >>= 1) {
        s += __shfl_xor_sync(~0u, s, o);
        s2 += __shfl_xor_sync(~0u, s2, o);
    }
    if (!lane) { ssum[w] = s; ssum2[w] = s2; }
    __syncthreads();
    if (threadIdx.x == 0) {
        float a = 0.f, bb = 0.f;
#pragma unroll
        for (int i = 0; i < 8; i++) { a += ssum[i]; bb += ssum2[i]; }
        float mean = a * (1.f / DD);
        float var = bb * (1.f / DD) - mean * mean;
        smean = mean; srstd = rsqrtf(var + 1e-5f);
    }
    __syncthreads();
    float4 g4 = ((const float4*)gam)[threadIdx.x];
    float4 b4 = ((const float4*)bet)[threadIdx.x];
    float m = smean, rs = srstd;
    float4 o4;
    o4.x = (vv.x - m) * rs * g4.x + b4.x;
    o4.y = (vv.y - m) * rs * g4.y + b4.y;
    o4.z = (vv.z - m) * rs * g4.z + b4.z;
    o4.w = (vv.w - m) * rs * g4.w + b4.w;
    ((float4*)(out + (size_t)t * DD))[threadIdx.x] = o4;
}

// ---------------- gate ----------------
__global__ void zero_counts_kernel() {
    if (threadIdx.x < EE) g_counts[threadIdx.x] = 0;
}

__global__ void gate_kernel(const float* __restrict__ x1,
                            const float* __restrict__ gw,
                            const float* __restrict__ gb)
{
    int t = blockIdx.x * (blockDim.x / 32) + (threadIdx.x >> 5);
    int lane = threadIdx.x & 31;
    float acc[EE] = {};
    const float* xr = x1 + (size_t)t * DD;
    for (int d = lane; d < DD; d += 32) {
        float xv = xr[d];
        const float* grow = gw + (size_t)d * EE;
#pragma unroll
        for (int e = 0; e < EE; e++) acc[e] += xv * grow[e];
    }
#pragma unroll
    for (int e = 0; e < EE; e++)
#pragma unroll
        for (int o = 16; o; o >>= 1) acc[e] += __shfl_xor_sync(~0u, acc[e], o);
    if (lane == 0) {
#pragma unroll
        for (int e = 0; e < EE; e++) acc[e] += gb[e];
        float best = -1e30f; int bi = 0;
#pragma unroll
        for (int e = 0; e < EE; e++)
            if (acc[e] > best) { best = acc[e]; bi = e; }
        float best2 = -1e30f; int bi2 = 0;
#pragma unroll
        for (int e = 0; e < EE; e++)
            if (e != bi && acc[e] > best2) { best2 = acc[e]; bi2 = e; }
        float w0 = 1.f / (1.f + __expf(best2 - best));
        g_gatew[2 * t] = w0;
        g_gatew[2 * t + 1] = 1.f - w0;
        int p0 = atomicAdd(&g_counts[bi], 1);
        g_list[bi * TT + p0] = 2 * t;
        int p1 = atomicAdd(&g_counts[bi2], 1);
        g_list[bi2 * TT + p1] = 2 * t + 1;
    }
}

// ---------------- combine experts + residual + LN3 -> out ----------------
__global__ void combine_ln_kernel(const float* __restrict__ x1,
                                  const float* __restrict__ gam,
                                  const float* __restrict__ bet,
                                  float* __restrict__ out)
{
    __shared__ float ssum[8], ssum2[8];
    __shared__ float smean, srstd;
    int t = blockIdx.x;
    float w0 = g_gatew[2 * t], w1 = g_gatew[2 * t + 1];
    const float4* xr = (const float4*)(x1 + (size_t)t * DD);
    const float4* y0 = (const float4*)(g_y + (size_t)(2 * t) * DD);
    const float4* y1 = (const float4*)(g_y + (size_t)(2 * t + 1) * DD);
    float4 a = xr[threadIdx.x];
    float4 c0 = y0[threadIdx.x];
    float4 c1 = y1[threadIdx.x];
    float4 vv;
    vv.x = a.x + w0 * c0.x + w1 * c1.x;
    vv.y = a.y + w0 * c0.y + w1 * c1.y;
    vv.z = a.z + w0 * c0.z + w1 * c1.z;
    vv.w = a.w + w0 * c0.w + w1 * c1.w;
    float s = vv.x + vv.y + vv.z + vv.w;
    float s2 = vv.x * vv.x + vv.y * vv.y + vv.z * vv.z + vv.w * vv.w;
    int lane = threadIdx.x & 31, w = threadIdx.x >> 5;
#pragma unroll
    for (int o = 16; o; o >>= 1) {
        s += __shfl_xor_sync(~0u, s, o);
        s2 += __shfl_xor_sync(~0u, s2, o);
    }
    if (!lane) { ssum[w] = s; ssum2[w] = s2; }
    __syncthreads();
    if (threadIdx.x == 0) {
        float aa = 0.f, bb = 0.f;
#pragma unroll
        for (int i = 0; i < 8; i++) { aa += ssum[i]; bb += ssum2[i]; }
        float mean = aa * (1.f / DD);
        float var = bb * (1.f / DD) - mean * mean;
        smean = mean; srstd = rsqrtf(var + 1e-5f);
    }
    __syncthreads();
    float4 g4 = ((const float4*)gam)[threadIdx.x];
    float4 b4 = ((const float4*)bet)[threadIdx.x];
    float m = smean, rs = srstd;
    float4 o4;
    o4.x = (vv.x - m) * rs * g4.x + b4.x;
    o4.y = (vv.y - m) * rs * g4.y + b4.y;
    o4.z = (vv.z - m) * rs * g4.z + b4.z;
    o4.w = (vv.w - m) * rs * g4.w + b4.w;
    ((float4*)(out + (size_t)t * DD))[threadIdx.x] = o4;
}

// ---------------- launch ----------------
extern "C" void kernel_launch(void* const* d_in, const int* in_sizes, int n_in,
                              void* d_out, int out_size)
{
    const float* x    = (const float*)d_in[0];
    const float* Wq   = (const float*)d_in[1];
    const float* bq   = (const float*)d_in[2];
    const float* Wk   = (const float*)d_in[3];
    const float* bk   = (const float*)d_in[4];
    const float* Wv   = (const float*)d_in[5];
    const float* bv   = (const float*)d_in[6];
    const float* Wo   = (const float*)d_in[7];
    const float* bo   = (const float*)d_in[8];
    const float* ln1g = (const float*)d_in[9];
    const float* ln1b = (const float*)d_in[10];
    const float* gw   = (const float*)d_in[11];
    const float* gb   = (const float*)d_in[12];
    const float* W1   = (const float*)d_in[13];
    const float* b1   = (const float*)d_in[14];
    const float* W2   = (const float*)d_in[15];
    const float* b2   = (const float*)d_in[16];
    const float* ln3g = (const float*)d_in[17];
    const float* ln3b = (const float*)d_in[18];
    float* out = (float*)d_out;

    static int attr_set = 0;
    if (!attr_set) {
        cudaFuncSetAttribute(mm_mma_kernel, cudaFuncAttributeMaxDynamicSharedMemorySize, MMA_SMEM);
        attr_set = 1;
    }

    float *pqkv, *pctx, *pres1, *px1, *pact, *py, *pw1T, *pw2T;
    int *pcounts, *plist;
    cudaGetSymbolAddress((void**)&pqkv, g_qkv);
    cudaGetSymbolAddress((void**)&pctx, g_ctx);
    cudaGetSymbolAddress((void**)&pres1, g_res1);
    cudaGetSymbolAddress((void**)&px1, g_x1);
    cudaGetSymbolAddress((void**)&pact, g_act);
    cudaGetSymbolAddress((void**)&py, g_y);
    cudaGetSymbolAddress((void**)&pw1T, g_w1T);
    cudaGetSymbolAddress((void**)&pw2T, g_w2T);
    cudaGetSymbolAddress((void**)&pcounts, g_counts);
    cudaGetSymbolAddress((void**)&plist, g_list);

    dim3 tb(32, 8);
    // MoE weight transposes: W1 [E][D][F] -> [E][F][D]; W2 [E][F][D] -> [E][D][F]
    transpose_kernel<<<dim3(FF / 32, DD / 32, EE), tb>>>(W1, pw1T, DD, FF);
    transpose_kernel<<<dim3(DD / 32, FF / 32, EE), tb>>>(W2, pw2T, FF, DD);

    // QKV projections (fp32 exact)
    dim3 gqkv(DD / BN, TT / BM, 1);
    gemm_kernel<<<gqkv, 256>>>(x, Wq, bq, nullptr, pqkv, TT, DD, DD);
    gemm_kernel<<<gqkv, 256>>>(x, Wk, bk, nullptr, pqkv + (size_t)TT * DD, TT, DD, DD);
    gemm_kernel<<<gqkv, 256>>>(x, Wv, bv, nullptr, pqkv + 2u * TT * DD, TT, DD, DD);

    // attention
    attn_kernel<<<dim3(SS / 64, HH, 2), 256>>>(pqkv, pqkv + (size_t)TT * DD,
                                               pqkv + 2u * TT * DD, pctx);

    // O projection + residual (fp32 exact)
    gemm_kernel<<<gqkv, 256>>>(pctx, Wo, bo, x, pres1, TT, DD, DD);

    // LN1
    ln_kernel<<<TT, 256>>>(pres1, ln1g, ln1b, px1);

    // gate + dispatch (fp32 exact -> no expert flips)
    zero_counts_kernel<<<1, 32>>>();
    gate_kernel<<<TT / 8, 256>>>(px1, gw, gb);

    // FFN1 (tf32 mma, gathered): g_act[entry] = act(x1[tok] @ W1[e] + b1[e])
    mm_mma_kernel<<<dim3(FF / 128, TT / 128, EE), 256, MMA_SMEM>>>(
        px1, pw1T, b1, pact, TT, DD, FF, DD, FF, plist, pcounts, 1, 3);

    // FFN2 (tf32 mma, gathered): g_y[entry] = g_act[entry] @ W2[e] + b2[e]
    mm_mma_kernel<<<dim3(DD / 128, TT / 128, EE), 256, MMA_SMEM>>>(
        pact, pw2T, b2, py, TT, FF, DD, FF, DD, plist, pcounts, 0, 0);

    // combine + residual + LN3 -> out
    combine_ln_kernel<<<TT, 256>>>(px1, ln3g, ln3b, out);
}

// round 4
// speedup vs baseline: 2.7826x; 1.2525x over previous
#include <cuda_runtime.h>
#include <cuda_bf16.h>
#include <math.h>
#include <stdint.h>

// Problem constants
#define TT 4096   // B*S tokens
#define DD 1024   // d_model
#define FF 4096   // d_ff
#define EE 8      // experts
#define SS 2048   // seq
#define HH 16     // heads
#define DK 64     // head dim

// ---------------- scratch ----------------
__device__ float g_qkv[3u * TT * DD];
__device__ float g_ctx[TT * DD];
__device__ float g_res1[TT * DD];
__device__ float g_x1[TT * DD];
__device__ float g_act[2u * TT * FF];
__device__ float g_y[2u * TT * DD];
__device__ float g_gatew[2 * TT];
__device__ int   g_counts[EE];
__device__ int   g_list[EE * TT];
__device__ float g_w1T[(size_t)EE * DD * FF];   // [E][F][D]
__device__ float g_w2T[(size_t)EE * FF * DD];   // [E][D][F]
__device__ float g_wqkvT[3u * DD * DD];         // [3][D_out][D_in]
__device__ float g_woT[DD * DD];
__device__ float g_bqkv[3 * DD];

// ---------------- common helpers ----------------
#define LDP 36
#define TILE_F (128 * LDP)
#define MMA_SMEM (2 * 2 * TILE_F * 4)   // 73728 bytes

__device__ __forceinline__ uint32_t smem_u32(const void* p) {
    uint32_t a;
    asm("{ .reg .u64 t; cvta.to.shared.u64 t, %1; cvt.u32.u64 %0, t; }" : "=r"(a) : "l"(p));
    return a;
}
__device__ __forceinline__ void cp16(uint32_t dst, const void* src) {
    asm volatile("cp.async.cg.shared.global [%0], [%1], 16;" :: "r"(dst), "l"(src));
}
__device__ __forceinline__ void cp16z(uint32_t dst, const void* src, int sz) {
    asm volatile("cp.async.cg.shared.global [%0], [%1], 16, %2;" :: "r"(dst), "l"(src), "r"(sz));
}
__device__ __forceinline__ void cp_commit() { asm volatile("cp.async.commit_group;"); }
__device__ __forceinline__ void cp_wait1() { asm volatile("cp.async.wait_group 1;" ::: "memory"); }
__device__ __forceinline__ void cp_wait0() { asm volatile("cp.async.wait_group 0;" ::: "memory"); }
__device__ __forceinline__ void mma_tf32(float* d, const float* a, const float* b) {
    asm volatile(
        "mma.sync.aligned.m16n8k8.row.col.f32.tf32.tf32.f32 "
        "{%0,%1,%2,%3}, {%4,%5,%6,%7}, {%8,%9}, {%0,%1,%2,%3};"
        : "+f"(d[0]), "+f"(d[1]), "+f"(d[2]), "+f"(d[3])
        : "r"(__float_as_uint(a[0])), "r"(__float_as_uint(a[1])),
          "r"(__float_as_uint(a[2])), "r"(__float_as_uint(a[3])),
          "r"(__float_as_uint(b[0])), "r"(__float_as_uint(b[1])));
}
__device__ __forceinline__ float tf32_hi(float a) {
    uint32_t r;
    asm("cvt.rna.tf32.f32 %0, %1;" : "=r"(r) : "f"(a));
    return __uint_as_float(r);
}

// ================= tf32 mma GEMM for MoE FFN (plain tf32, gathered A) =======
__global__ void __launch_bounds__(256)
mm_mma_kernel(const float* __restrict__ A,
              const float* __restrict__ WT,        // [E][N][K]
              const float* __restrict__ biasBase,  // [E][N]
              float* __restrict__ C,
              int M, int K, int N, int lda, int ldc,
              const int* __restrict__ listBase, const int* __restrict__ counts,
              int a_shift, int actmode)
{
    int e = blockIdx.z;
    const int* list = listBase + e * TT;
    int Me = counts[e];
    int m0 = blockIdx.y * 128;
    if (m0 >= Me) return;
    int n0 = blockIdx.x * 128;
    const float* W = WT + (size_t)e * N * K;
    const float* bias = biasBase + (size_t)e * N;

    extern __shared__ float smf[];
    float* As = smf;
    float* Bs = smf + 2 * TILE_F;
    uint32_t uA = smem_u32(As);
    uint32_t uB = smem_u32(Bs);

    __shared__ int rows_s[128];
    __shared__ int crows_s[128];

    int tid = threadIdx.x;
    if (tid < 128) {
        int m = m0 + tid;
        int r = -1, cr = -1;
        if (m < Me) { int ent = list[m]; r = ent >> a_shift; cr = ent; }
        rows_s[tid] = r; crows_s[tid] = cr;
    }
    __syncthreads();

    auto load_stage = [&](int s, int k0) {
#pragma unroll
        for (int i = 0; i < 4; i++) {
            int chunk = tid + i * 256;
            int row = chunk >> 3;
            int kc = chunk & 7;
            uint32_t off = (uint32_t)(s * TILE_F + row * LDP + kc * 4) * 4u;
            int ar = rows_s[row];
            const float* srcA = (ar >= 0) ? A + (size_t)ar * lda + k0 + kc * 4 : A;
            cp16z(uA + off, srcA, (ar >= 0) ? 16 : 0);
            const float* srcB = W + (size_t)(n0 + row) * K + k0 + kc * 4;
            cp16(uB + off, srcB);
        }
    };

    int NC = K >> 5;
    load_stage(0, 0); cp_commit();
    load_stage(1, 32); cp_commit();

    int w = tid >> 5, lane = tid & 31;
    int wm = w & 3, wn = w >> 2;
    int g = lane >> 2, ct = lane & 3;

    float acc[2][8][4];
#pragma unroll
    for (int mi = 0; mi < 2; mi++)
#pragma unroll
        for (int ni = 0; ni < 8; ni++)
#pragma unroll
            for (int j = 0; j < 4; j++) acc[mi][ni][j] = 0.f;

    for (int i = 0; i < NC; i++) {
        if (i + 1 < NC) cp_wait1(); else cp_wait0();
        __syncthreads();
        const float* Aw = As + (i & 1) * TILE_F;
        const float* Bw = Bs + (i & 1) * TILE_F;
#pragma unroll
        for (int ks = 0; ks < 4; ks++) {
            int kc = ks * 8 + ct;
            float afr[2][4];
#pragma unroll
            for (int mi = 0; mi < 2; mi++) {
                int rb = wm * 32 + mi * 16;
                afr[mi][0] = Aw[(rb + g) * LDP + kc];
                afr[mi][1] = Aw[(rb + g + 8) * LDP + kc];
                afr[mi][2] = Aw[(rb + g) * LDP + kc + 4];
                afr[mi][3] = Aw[(rb + g + 8) * LDP + kc + 4];
            }
            float bfr[8][2];
#pragma unroll
            for (int ni = 0; ni < 8; ni++) {
                int nb = wn * 64 + ni * 8;
                bfr[ni][0] = Bw[(nb + g) * LDP + kc];
                bfr[ni][1] = Bw[(nb + g) * LDP + kc + 4];
            }
#pragma unroll
            for (int mi = 0; mi < 2; mi++)
#pragma unroll
                for (int ni = 0; ni < 8; ni++)
                    mma_tf32(acc[mi][ni], afr[mi], bfr[ni]);
        }
        __syncthreads();
        if (i + 2 < NC) { load_stage(i & 1, (i + 2) << 5); cp_commit(); }
    }

    int act = (actmode == 3) ? ((e & 1) ? 2 : 1) : actmode;
#pragma unroll
    for (int mi = 0; mi < 2; mi++) {
#pragma unroll
        for (int h = 0; h < 2; h++) {
            int rl = wm * 32 + mi * 16 + g + h * 8;
            int crow = crows_s[rl];
            if (crow < 0) continue;
            float* Crow = C + (size_t)crow * ldc;
#pragma unroll
            for (int ni = 0; ni < 8; ni++) {
                int col = n0 + wn * 64 + ni * 8 + 2 * ct;
                float v0 = acc[mi][ni][2 * h + 0] + bias[col];
                float v1 = acc[mi][ni][2 * h + 1] + bias[col + 1];
                if (act == 1) {
                    v0 = 0.5f * v0 * (1.f + erff(v0 * 0.70710678118654752f));
                    v1 = 0.5f * v1 * (1.f + erff(v1 * 0.70710678118654752f));
                } else if (act == 2) {
                    v0 = v0 / (1.f + __expf(-v0));
                    v1 = v1 / (1.f + __expf(-v1));
                }
                *(float2*)&Crow[col] = make_float2(v0, v1);
            }
        }
    }
}

// ========== 3xTF32 split GEMM (fp32-accurate; dense A) for QKV / O ==========
// C[z][m][n] = A[m,:] @ WT[z][n,:] + bias[z][n] (+ resid[m][n])
__global__ void __launch_bounds__(256)
mm_split_kernel(const float* __restrict__ A,
                const float* __restrict__ WTbase,   // [Z][N][K]
                const float* __restrict__ biasBase, // [Z][N]
                const float* __restrict__ resid,    // or null
                float* __restrict__ Cbase,          // [Z][M][N]
                int K, int N)
{
    int z = blockIdx.z;
    int m0 = blockIdx.y * 128;
    int n0 = blockIdx.x * 128;
    const float* W = WTbase + (size_t)z * N * K;
    const float* bias = biasBase + (size_t)z * N;
    float* C = Cbase + (size_t)z * TT * N;

    extern __shared__ float smf[];
    float* As = smf;
    float* Bs = smf + 2 * TILE_F;
    uint32_t uA = smem_u32(As);
    uint32_t uB = smem_u32(Bs);

    int tid = threadIdx.x;

    auto load_stage = [&](int s, int k0) {
#pragma unroll
        for (int i = 0; i < 4; i++) {
            int chunk = tid + i * 256;
            int row = chunk >> 3;
            int kc = chunk & 7;
            uint32_t off = (uint32_t)(s * TILE_F + row * LDP + kc * 4) * 4u;
            cp16(uA + off, A + (size_t)(m0 + row) * K + k0 + kc * 4);
            cp16(uB + off, W + (size_t)(n0 + row) * K + k0 + kc * 4);
        }
    };

    int NC = K >> 5;
    load_stage(0, 0); cp_commit();
    load_stage(1, 32); cp_commit();

    int w = tid >> 5, lane = tid & 31;
    int wm = w & 3, wn = w >> 2;
    int g = lane >> 2, ct = lane & 3;

    float acc[2][8][4];
#pragma unroll
    for (int mi = 0; mi < 2; mi++)
#pragma unroll
        for (int ni = 0; ni < 8; ni++)
#pragma unroll
            for (int j = 0; j < 4; j++) acc[mi][ni][j] = 0.f;

    for (int i = 0; i < NC; i++) {
        if (i + 1 < NC) cp_wait1(); else cp_wait0();
        __syncthreads();
        const float* Aw = As + (i & 1) * TILE_F;
        const float* Bw = Bs + (i & 1) * TILE_F;
#pragma unroll
        for (int ks = 0; ks < 4; ks++) {
            int kc = ks * 8 + ct;
            float ah[2][4], al[2][4];
#pragma unroll
            for (int mi = 0; mi < 2; mi++) {
                int rb = wm * 32 + mi * 16;
                float a0 = Aw[(rb + g) * LDP + kc];
                float a1 = Aw[(rb + g + 8) * LDP + kc];
                float a2 = Aw[(rb + g) * LDP + kc + 4];
                float a3 = Aw[(rb + g + 8) * LDP + kc + 4];
                ah[mi][0] = tf32_hi(a0); al[mi][0] = a0 - ah[mi][0];
                ah[mi][1] = tf32_hi(a1); al[mi][1] = a1 - ah[mi][1];
                ah[mi][2] = tf32_hi(a2); al[mi][2] = a2 - ah[mi][2];
                ah[mi][3] = tf32_hi(a3); al[mi][3] = a3 - ah[mi][3];
            }
            float bh[8][2], bl[8][2];
#pragma unroll
            for (int ni = 0; ni < 8; ni++) {
                int nb = wn * 64 + ni * 8;
                float b0 = Bw[(nb + g) * LDP + kc];
                float b1 = Bw[(nb + g) * LDP + kc + 4];
                bh[ni][0] = tf32_hi(b0); bl[ni][0] = b0 - bh[ni][0];
                bh[ni][1] = tf32_hi(b1); bl[ni][1] = b1 - bh[ni][1];
            }
#pragma unroll
            for (int mi = 0; mi < 2; mi++)
#pragma unroll
                for (int ni = 0; ni < 8; ni++) {
                    mma_tf32(acc[mi][ni], ah[mi], bl[ni]);
                    mma_tf32(acc[mi][ni], al[mi], bh[ni]);
                    mma_tf32(acc[mi][ni], ah[mi], bh[ni]);
                }
        }
        __syncthreads();
        if (i + 2 < NC) { load_stage(i & 1, (i + 2) << 5); cp_commit(); }
    }

#pragma unroll
    for (int mi = 0; mi < 2; mi++) {
#pragma unroll
        for (int h = 0; h < 2; h++) {
            int m = m0 + wm * 32 + mi * 16 + g + h * 8;
            float* Crow = C + (size_t)m * N;
            const float* rrow = resid ? resid + (size_t)m * N : nullptr;
#pragma unroll
            for (int ni = 0; ni < 8; ni++) {
                int col = n0 + wn * 64 + ni * 8 + 2 * ct;
                float v0 = acc[mi][ni][2 * h + 0] + bias[col];
                float v1 = acc[mi][ni][2 * h + 1] + bias[col + 1];
                if (rrow) { v0 += rrow[col]; v1 += rrow[col + 1]; }
                *(float2*)&Crow[col] = make_float2(v0, v1);
            }
        }
    }
}

// ---------------- transpose [R][C] -> [C][R] (per z slice) ----------------
__global__ void transpose_kernel(const float* __restrict__ in, float* __restrict__ out,
                                 int R, int C)
{
    __shared__ float t[32][33];
    const float* ip = in + (size_t)blockIdx.z * R * C;
    float* op = out + (size_t)blockIdx.z * R * C;
    int x = blockIdx.x * 32 + threadIdx.x;
    int y = blockIdx.y * 32 + threadIdx.y;
#pragma unroll
    for (int i = 0; i < 4; i++)
        t[threadIdx.y + i * 8][threadIdx.x] = ip[(size_t)(y + i * 8) * C + x];
    __syncthreads();
    int x2 = blockIdx.y * 32 + threadIdx.x;
    int y2 = blockIdx.x * 32 + threadIdx.y;
#pragma unroll
    for (int i = 0; i < 4; i++)
        op[(size_t)(y2 + i * 8) * R + x2] = t[threadIdx.x][threadIdx.y + i * 8];
}

__global__ void concat_bias_kernel(const float* bq, const float* bk, const float* bv,
                                   float* out)
{
    int i = blockIdx.x * 256 + threadIdx.x;
    if (i < DD) { out[i] = bq[i]; out[DD + i] = bk[i]; out[2 * DD + i] = bv[i]; }
}

// ---------------- flash attention (fp32) ----------------
__global__ void attn_kernel(const float* __restrict__ q,
                            const float* __restrict__ k,
                            const float* __restrict__ v,
                            float* __restrict__ ctx)
{
    int qt = blockIdx.x, h = blockIdx.y, b = blockIdx.z;
    int tid = threadIdx.x;
    int tx = tid & 15, ty = tid >> 4;

    __shared__ float Qt[64][64];
    __shared__ float Ks[32][65];
    __shared__ float Vs[32][64];
    __shared__ float Ps[64][33];

    size_t base = ((size_t)b * SS) * DD + (size_t)h * DK;
    const float* qb = q + base + (size_t)qt * 64 * DD;
    const float* kb = k + base;
    const float* vb = v + base;

#pragma unroll
    for (int i = 0; i < 16; i++) {
        int idx = tid + i * 256;
        int row = idx >> 6, col = idx & 63;
        Qt[col][row] = qb[(size_t)row * DD + col];
    }
    __syncthreads();

    float acc[4][4] = {};
    float mrow[4], lrow[4];
#pragma unroll
    for (int i = 0; i < 4; i++) { mrow[i] = -1e30f; lrow[i] = 0.f; }
    const float scale = 0.125f;

    for (int k0 = 0; k0 < SS; k0 += 32) {
#pragma unroll
        for (int i = 0; i < 8; i++) {
            int idx = tid + i * 256;
            int row = idx >> 6, col = idx & 63;
            Ks[row][col] = kb[(size_t)(k0 + row) * DD + col];
            Vs[row][col] = vb[(size_t)(k0 + row) * DD + col];
        }
        __syncthreads();

        float s[4][2] = {};
#pragma unroll
        for (int kk = 0; kk < 64; kk++) {
            float4 q4 = *(const float4*)&Qt[kk][ty * 4];
            float k0v = Ks[tx * 2][kk];
            float k1v = Ks[tx * 2 + 1][kk];
            s[0][0] += q4.x * k0v; s[0][1] += q4.x * k1v;
            s[1][0] += q4.y * k0v; s[1][1] += q4.y * k1v;
            s[2][0] += q4.z * k0v; s[2][1] += q4.z * k1v;
            s[3][0] += q4.w * k0v; s[3][1] += q4.w * k1v;
        }
#pragma unroll
        for (int i = 0; i < 4; i++) { s[i][0] *= scale; s[i][1] *= scale; }

#pragma unroll
        for (int i = 0; i < 4; i++) {
            float rm = fmaxf(s[i][0], s[i][1]);
#pragma unroll
            for (int o = 1; o < 16; o <<= 1)
                rm = fmaxf(rm, __shfl_xor_sync(0xffffffffu, rm, o));
            float mnew = fmaxf(mrow[i], rm);
            float corr = __expf(mrow[i] - mnew);
            float p0 = __expf(s[i][0] - mnew);
            float p1 = __expf(s[i][1] - mnew);
            float rs = p0 + p1;
#pragma unroll
            for (int o = 1; o < 16; o <<= 1)
                rs += __shfl_xor_sync(0xffffffffu, rs, o);
            lrow[i] = lrow[i] * corr + rs;
            mrow[i] = mnew;
#pragma unroll
            for (int j = 0; j < 4; j++) acc[i][j] *= corr;
            Ps[ty * 4 + i][tx * 2] = p0;
            Ps[ty * 4 + i][tx * 2 + 1] = p1;
        }
        __syncthreads();

#pragma unroll
        for (int kk = 0; kk < 32; kk++) {
            float4 v4 = *(const float4*)&Vs[kk][tx * 4];
            float p[4];
#pragma unroll
            for (int i = 0; i < 4; i++) p[i] = Ps[ty * 4 + i][kk];
#pragma unroll
            for (int i = 0; i < 4; i++) {
                acc[i][0] += p[i] * v4.x;
                acc[i][1] += p[i] * v4.y;
                acc[i][2] += p[i] * v4.z;
                acc[i][3] += p[i] * v4.w;
            }
        }
        __syncthreads();
    }

    float* cb = ctx + base + (size_t)qt * 64 * DD;
#pragma unroll
    for (int i = 0; i < 4; i++) {
        float inv = 1.f / lrow[i];
        int qrow = ty * 4 + i;
        *(float4*)&cb[(size_t)qrow * DD + tx * 4] =
            make_float4(acc[i][0] * inv, acc[i][1] * inv,
                        acc[i][2] * inv, acc[i][3] * inv);
    }
}

// ---------------- layernorm ----------------
__global__ void ln_kernel(const float* __restrict__ in,
                          const float* __restrict__ gam,
                          const float* __restrict__ bet,
                          float* __restrict__ out)
{
    __shared__ float ssum[8], ssum2[8];
    __shared__ float smean, srstd;
    int t = blockIdx.x;
    const float4* r = (const float4*)(in + (size_t)t * DD);
    float4 vv = r[threadIdx.x];
    float s = vv.x + vv.y + vv.z + vv.w;
    float s2 = vv.x * vv.x + vv.y * vv.y + vv.z * vv.z + vv.w * vv.w;
    int lane = threadIdx.x & 31, w = threadIdx.x >> 5;
#pragma unroll
    for (int o = 16; o; o >>= 1) {
        s += __shfl_xor_sync(~0u, s, o);
        s2 += __shfl_xor_sync(~0u, s2, o);
    }
    if (!lane) { ssum[w] = s; ssum2[w] = s2; }
    __syncthreads();
    if (threadIdx.x == 0) {
        float a = 0.f, bb = 0.f;
#pragma unroll
        for (int i = 0; i < 8; i++) { a += ssum[i]; bb += ssum2[i]; }
        float mean = a * (1.f / DD);
        float var = bb * (1.f / DD) - mean * mean;
        smean = mean; srstd = rsqrtf(var + 1e-5f);
    }
    __syncthreads();
    float4 g4 = ((const float4*)gam)[threadIdx.x];
    float4 b4 = ((const float4*)bet)[threadIdx.x];
    float m = smean, rs = srstd;
    float4 o4;
    o4.x = (vv.x - m) * rs * g4.x + b4.x;
    o4.y = (vv.y - m) * rs * g4.y + b4.y;
    o4.z = (vv.z - m) * rs * g4.z + b4.z;
    o4.w = (vv.w - m) * rs * g4.w + b4.w;
    ((float4*)(out + (size_t)t * DD))[threadIdx.x] = o4;
}

// ---------------- gate ----------------
__global__ void zero_counts_kernel() {
    if (threadIdx.x < EE) g_counts[threadIdx.x] = 0;
}

__global__ void gate_kernel(const float* __restrict__ x1,
                            const float* __restrict__ gw,
                            const float* __restrict__ gb)
{
    int t = blockIdx.x * (blockDim.x / 32) + (threadIdx.x >> 5);
    int lane = threadIdx.x & 31;
    float acc[EE] = {};
    const float* xr = x1 + (size_t)t * DD;
    for (int d = lane; d < DD; d += 32) {
        float xv = xr[d];
        const float* grow = gw + (size_t)d * EE;
#pragma unroll
        for (int e = 0; e < EE; e++) acc[e] += xv * grow[e];
    }
#pragma unroll
    for (int e = 0; e < EE; e++)
#pragma unroll
        for (int o = 16; o; o >>= 1) acc[e] += __shfl_xor_sync(~0u, acc[e], o);
    if (lane == 0) {
#pragma unroll
        for (int e = 0; e < EE; e++) acc[e] += gb[e];
        float best = -1e30f; int bi = 0;
#pragma unroll
        for (int e = 0; e < EE; e++)
            if (acc[e] > best) { best = acc[e]; bi = e; }
        float best2 = -1e30f; int bi2 = 0;
#pragma unroll
        for (int e = 0; e < EE; e++)
            if (e != bi && acc[e] > best2) { best2 = acc[e]; bi2 = e; }
        float w0 = 1.f / (1.f + __expf(best2 - best));
        g_gatew[2 * t] = w0;
        g_gatew[2 * t + 1] = 1.f - w0;
        int p0 = atomicAdd(&g_counts[bi], 1);
        g_list[bi * TT + p0] = 2 * t;
        int p1 = atomicAdd(&g_counts[bi2], 1);
        g_list[bi2 * TT + p1] = 2 * t + 1;
    }
}

// ---------------- combine experts + residual + LN3 -> out ----------------
__global__ void combine_ln_kernel(const float* __restrict__ x1,
                                  const float* __restrict__ gam,
                                  const float* __restrict__ bet,
                                  float* __restrict__ out)
{
    __shared__ float ssum[8], ssum2[8];
    __shared__ float smean, srstd;
    int t = blockIdx.x;
    float w0 = g_gatew[2 * t], w1 = g_gatew[2 * t + 1];
    const float4* xr = (const float4*)(x1 + (size_t)t * DD);
    const float4* y0 = (const float4*)(g_y + (size_t)(2 * t) * DD);
    const float4* y1 = (const float4*)(g_y + (size_t)(2 * t + 1) * DD);
    float4 a = xr[threadIdx.x];
    float4 c0 = y0[threadIdx.x];
    float4 c1 = y1[threadIdx.x];
    float4 vv;
    vv.x = a.x + w0 * c0.x + w1 * c1.x;
    vv.y = a.y + w0 * c0.y + w1 * c1.y;
    vv.z = a.z + w0 * c0.z + w1 * c1.z;
    vv.w = a.w + w0 * c0.w + w1 * c1.w;
    float s = vv.x + vv.y + vv.z + vv.w;
    float s2 = vv.x * vv.x + vv.y * vv.y + vv.z * vv.z + vv.w * vv.w;
    int lane = threadIdx.x & 31, w = threadIdx.x >> 5;
#pragma unroll
    for (int o = 16; o; o >>= 1) {
        s += __shfl_xor_sync(~0u, s, o);
        s2 += __shfl_xor_sync(~0u, s2, o);
    }
    if (!lane) { ssum[w] = s; ssum2[w] = s2; }
    __syncthreads();
    if (threadIdx.x == 0) {
        float aa = 0.f, bb = 0.f;
#pragma unroll
        for (int i = 0; i < 8; i++) { aa += ssum[i]; bb += ssum2[i]; }
        float mean = aa * (1.f / DD);
        float var = bb * (1.f / DD) - mean * mean;
        smean = mean; srstd = rsqrtf(var + 1e-5f);
    }
    __syncthreads();
    float4 g4 = ((const float4*)gam)[threadIdx.x];
    float4 b4 = ((const float4*)bet)[threadIdx.x];
    float m = smean, rs = srstd;
    float4 o4;
    o4.x = (vv.x - m) * rs * g4.x + b4.x;
    o4.y = (vv.y - m) * rs * g4.y + b4.y;
    o4.z = (vv.z - m) * rs * g4.z + b4.z;
    o4.w = (vv.w - m) * rs * g4.w + b4.w;
    ((float4*)(out + (size_t)t * DD))[threadIdx.x] = o4;
}

// ---------------- launch ----------------
extern "C" void kernel_launch(void* const* d_in, const int* in_sizes, int n_in,
                              void* d_out, int out_size)
{
    const float* x    = (const float*)d_in[0];
    const float* Wq   = (const float*)d_in[1];
    const float* bq   = (const float*)d_in[2];
    const float* Wk   = (const float*)d_in[3];
    const float* bk   = (const float*)d_in[4];
    const float* Wv   = (const float*)d_in[5];
    const float* bv   = (const float*)d_in[6];
    const float* Wo   = (const float*)d_in[7];
    const float* bo   = (const float*)d_in[8];
    const float* ln1g = (const float*)d_in[9];
    const float* ln1b = (const float*)d_in[10];
    const float* gw   = (const float*)d_in[11];
    const float* gb   = (const float*)d_in[12];
    const float* W1   = (const float*)d_in[13];
    const float* b1   = (const float*)d_in[14];
    const float* W2   = (const float*)d_in[15];
    const float* b2   = (const float*)d_in[16];
    const float* ln3g = (const float*)d_in[17];
    const float* ln3b = (const float*)d_in[18];
    float* out = (float*)d_out;

    static int attr_set = 0;
    if (!attr_set) {
        cudaFuncSetAttribute(mm_mma_kernel, cudaFuncAttributeMaxDynamicSharedMemorySize, MMA_SMEM);
        cudaFuncSetAttribute(mm_split_kernel, cudaFuncAttributeMaxDynamicSharedMemorySize, MMA_SMEM);
        attr_set = 1;
    }

    float *pqkv, *pctx, *pres1, *px1, *pact, *py, *pw1T, *pw2T, *pwqkvT, *pwoT, *pbqkv;
    int *pcounts, *plist;
    cudaGetSymbolAddress((void**)&pqkv, g_qkv);
    cudaGetSymbolAddress((void**)&pctx, g_ctx);
    cudaGetSymbolAddress((void**)&pres1, g_res1);
    cudaGetSymbolAddress((void**)&px1, g_x1);
    cudaGetSymbolAddress((void**)&pact, g_act);
    cudaGetSymbolAddress((void**)&py, g_y);
    cudaGetSymbolAddress((void**)&pw1T, g_w1T);
    cudaGetSymbolAddress((void**)&pw2T, g_w2T);
    cudaGetSymbolAddress((void**)&pwqkvT, g_wqkvT);
    cudaGetSymbolAddress((void**)&pwoT, g_woT);
    cudaGetSymbolAddress((void**)&pbqkv, g_bqkv);
    cudaGetSymbolAddress((void**)&pcounts, g_counts);
    cudaGetSymbolAddress((void**)&plist, g_list);

    dim3 tb(32, 8);
    // weight transposes to K-major [N][K]
    transpose_kernel<<<dim3(DD / 32, DD / 32, 1), tb>>>(Wq, pwqkvT, DD, DD);
    transpose_kernel<<<dim3(DD / 32, DD / 32, 1), tb>>>(Wk, pwqkvT + DD * DD, DD, DD);
    transpose_kernel<<<dim3(DD / 32, DD / 32, 1), tb>>>(Wv, pwqkvT + 2 * DD * DD, DD, DD);
    transpose_kernel<<<dim3(DD / 32, DD / 32, 1), tb>>>(Wo, pwoT, DD, DD);
    transpose_kernel<<<dim3(FF / 32, DD / 32, EE), tb>>>(W1, pw1T, DD, FF);
    transpose_kernel<<<dim3(DD / 32, FF / 32, EE), tb>>>(W2, pw2T, FF, DD);
    concat_bias_kernel<<<4, 256>>>(bq, bk, bv, pbqkv);

    // QKV projections (3xTF32 split, fp32-accurate)
    mm_split_kernel<<<dim3(DD / 128, TT / 128, 3), 256, MMA_SMEM>>>(
        x, pwqkvT, pbqkv, nullptr, pqkv, DD, DD);

    // attention
    attn_kernel<<<dim3(SS / 64, HH, 2), 256>>>(pqkv, pqkv + (size_t)TT * DD,
                                               pqkv + 2u * TT * DD, pctx);

    // O projection + residual (3xTF32 split)
    mm_split_kernel<<<dim3(DD / 128, TT / 128, 1), 256, MMA_SMEM>>>(
        pctx, pwoT, bo, x, pres1, DD, DD);

    // LN1
    ln_kernel<<<TT, 256>>>(pres1, ln1g, ln1b, px1);

    // gate + dispatch
    zero_counts_kernel<<<1, 32>>>();
    gate_kernel<<<TT / 8, 256>>>(px1, gw, gb);

    // FFN1 (tf32 mma, gathered)
    mm_mma_kernel<<<dim3(FF / 128, TT / 128, EE), 256, MMA_SMEM>>>(
        px1, pw1T, b1, pact, TT, DD, FF, DD, FF, plist, pcounts, 1, 3);

    // FFN2 (tf32 mma, gathered)
    mm_mma_kernel<<<dim3(DD / 128, TT / 128, EE), 256, MMA_SMEM>>>(
        pact, pw2T, b2, py, TT, FF, DD, FF, DD, plist, pcounts, 0, 0);

    // combine + residual + LN3 -> out
    combine_ln_kernel<<<TT, 256>>>(px1, ln3g, ln3b, out);
}

// round 6
// speedup vs baseline: 3.3015x; 1.1865x over previous
#include <cuda_runtime.h>
#include <cuda_bf16.h>
#include <math.h>
#include <stdint.h>

// Problem constants
#define TT 4096   // B*S tokens
#define DD 1024   // d_model
#define FF 4096   // d_ff
#define EE 8      // experts
#define SS 2048   // seq
#define HH 16     // heads
#define DK 64     // head dim

// ---------------- scratch ----------------
__device__ float g_qkv[3u * TT * DD];
__device__ float g_ctx[TT * DD];
__device__ float g_res1[TT * DD];
__device__ float g_x1[TT * DD];
__device__ float g_act[2u * TT * FF];
__device__ float g_y[2u * TT * DD];
__device__ float g_gatew[2 * TT];
__device__ int   g_counts[EE];
__device__ int   g_list[EE * TT];

// ---------------- helpers ----------------
#define ALDP 36                    // A smem row pad (floats)
#define ASTG (128 * ALDP)          // A floats per stage
#define BLDN 136                   // B smem row pad (floats), rows are k
#define BSTG (32 * BLDN)           // B floats per stage
#define MMA_SMEM ((2 * ASTG + 2 * BSTG) * 4)   // 71680 bytes

__device__ __forceinline__ uint32_t smem_u32(const void* p) {
    uint32_t a;
    asm("{ .reg .u64 t; cvta.to.shared.u64 t, %1; cvt.u32.u64 %0, t; }" : "=r"(a) : "l"(p));
    return a;
}
__device__ __forceinline__ void cp16(uint32_t dst, const void* src) {
    asm volatile("cp.async.cg.shared.global [%0], [%1], 16;" :: "r"(dst), "l"(src));
}
__device__ __forceinline__ void cp16z(uint32_t dst, const void* src, int sz) {
    asm volatile("cp.async.cg.shared.global [%0], [%1], 16, %2;" :: "r"(dst), "l"(src), "r"(sz));
}
__device__ __forceinline__ void cp_commit() { asm volatile("cp.async.commit_group;"); }
__device__ __forceinline__ void cp_wait1() { asm volatile("cp.async.wait_group 1;" ::: "memory"); }
__device__ __forceinline__ void cp_wait0() { asm volatile("cp.async.wait_group 0;" ::: "memory"); }
__device__ __forceinline__ void mma_tf32(float* d, const float* a, const float* b) {
    asm volatile(
        "mma.sync.aligned.m16n8k8.row.col.f32.tf32.tf32.f32 "
        "{%0,%1,%2,%3}, {%4,%5,%6,%7}, {%8,%9}, {%0,%1,%2,%3};"
        : "+f"(d[0]), "+f"(d[1]), "+f"(d[2]), "+f"(d[3])
        : "r"(__float_as_uint(a[0])), "r"(__float_as_uint(a[1])),
          "r"(__float_as_uint(a[2])), "r"(__float_as_uint(a[3])),
          "r"(__float_as_uint(b[0])), "r"(__float_as_uint(b[1])));
}
__device__ __forceinline__ float tf32_hi(float a) {
    uint32_t r;
    asm("cvt.rna.tf32.f32 %0, %1;" : "=r"(r) : "f"(a));
    return __uint_as_float(r);
}
// fast exp for x <= 0 (clamped), ~1e-5 rel err, FMA-only (no MUFU)
__device__ __forceinline__ float fexp(float x) {
    float t = fmaxf(x * 1.4426950408889634f, -126.0f);
    float fl = floorf(t);
    float f = t - fl;
    float p = 1.53998500e-4f;
    p = fmaf(p, f, 1.33335581e-3f);
    p = fmaf(p, f, 9.61817007e-3f);
    p = fmaf(p, f, 5.55041087e-2f);
    p = fmaf(p, f, 2.40226507e-1f);
    p = fmaf(p, f, 6.93147182e-1f);
    p = fmaf(p, f, 1.0f);
    return __int_as_float(__float_as_int(p) + (((int)fl) << 23));
}

// ================= tf32 mma GEMM for MoE FFN (gathered A, row-major W) ======
// C[crow, n] = act( A[arow,:] @ W[e]  + bias[e] );  W native [E][K][N]
__global__ void __launch_bounds__(256)
mm_mma_kernel(const float* __restrict__ A,
              const float* __restrict__ Wbase,     // [E][K][N]
              const float* __restrict__ biasBase,  // [E][N]
              float* __restrict__ C,
              int M, int K, int N, int lda, int ldc,
              const int* __restrict__ listBase, const int* __restrict__ counts,
              int a_shift, int actmode)
{
    int e = blockIdx.z;
    const int* list = listBase + e * TT;
    int Me = counts[e];
    int m0 = blockIdx.y * 128;
    if (m0 >= Me) return;
    int n0 = blockIdx.x * 128;
    const float* W = Wbase + (size_t)e * K * N;
    const float* bias = biasBase + (size_t)e * N;

    extern __shared__ float smf[];
    float* As = smf;                    // [2][128][ALDP]
    float* Bs = smf + 2 * ASTG;         // [2][32][BLDN]
    uint32_t uA = smem_u32(As);
    uint32_t uB = smem_u32(Bs);

    __shared__ int rows_s[128];
    __shared__ int crows_s[128];

    int tid = threadIdx.x;
    if (tid < 128) {
        int m = m0 + tid;
        int r = -1, cr = -1;
        if (m < Me) { int ent = list[m]; r = ent >> a_shift; cr = ent; }
        rows_s[tid] = r; crows_s[tid] = cr;
    }
    __syncthreads();

    auto load_stage = [&](int s, int k0) {
#pragma unroll
        for (int i = 0; i < 4; i++) {
            int chunk = tid + i * 256;
            // A: 128 rows x 8 float4
            int row = chunk >> 3;
            int kc = chunk & 7;
            uint32_t offA = (uint32_t)(s * ASTG + row * ALDP + kc * 4) * 4u;
            int ar = rows_s[row];
            const float* srcA = (ar >= 0) ? A + (size_t)ar * lda + k0 + kc * 4 : A;
            cp16z(uA + offA, srcA, (ar >= 0) ? 16 : 0);
            // B: 32 k-rows x 32 float4 (row-major [K][N] from gmem)
            int brow = chunk >> 5;
            int bc = chunk & 31;
            uint32_t offB = (uint32_t)(s * BSTG + brow * BLDN + bc * 4) * 4u;
            cp16(uB + offB, W + (size_t)(k0 + brow) * N + n0 + bc * 4);
        }
    };

    int NC = K >> 5;
    load_stage(0, 0); cp_commit();
    load_stage(1, 32); cp_commit();

    int w = tid >> 5, lane = tid & 31;
    int wm = w & 3, wn = w >> 2;
    int g = lane >> 2, ct = lane & 3;

    float acc[2][8][4];
#pragma unroll
    for (int mi = 0; mi < 2; mi++)
#pragma unroll
        for (int ni = 0; ni < 8; ni++)
#pragma unroll
            for (int j = 0; j < 4; j++) acc[mi][ni][j] = 0.f;

    for (int i = 0; i < NC; i++) {
        if (i + 1 < NC) cp_wait1(); else cp_wait0();
        __syncthreads();
        const float* Aw = As + (i & 1) * ASTG;
        const float* Bw = Bs + (i & 1) * BSTG;
#pragma unroll
        for (int ks = 0; ks < 4; ks++) {
            int kc = ks * 8 + ct;
            float afr[2][4];
#pragma unroll
            for (int mi = 0; mi < 2; mi++) {
                int rb = wm * 32 + mi * 16;
                afr[mi][0] = Aw[(rb + g) * ALDP + kc];
                afr[mi][1] = Aw[(rb + g + 8) * ALDP + kc];
                afr[mi][2] = Aw[(rb + g) * ALDP + kc + 4];
                afr[mi][3] = Aw[(rb + g + 8) * ALDP + kc + 4];
            }
            const float* Br0 = Bw + (size_t)kc * BLDN;
            const float* Br1 = Bw + (size_t)(kc + 4) * BLDN;
            float bfr[8][2];
#pragma unroll
            for (int ni = 0; ni < 8; ni++) {
                int nc = wn * 64 + ni * 8 + g;
                bfr[ni][0] = Br0[nc];
                bfr[ni][1] = Br1[nc];
            }
#pragma unroll
            for (int mi = 0; mi < 2; mi++)
#pragma unroll
                for (int ni = 0; ni < 8; ni++)
                    mma_tf32(acc[mi][ni], afr[mi], bfr[ni]);
        }
        __syncthreads();
        if (i + 2 < NC) { load_stage(i & 1, (i + 2) << 5); cp_commit(); }
    }

    int act = (actmode == 3) ? ((e & 1) ? 2 : 1) : actmode;
#pragma unroll
    for (int mi = 0; mi < 2; mi++) {
#pragma unroll
        for (int h = 0; h < 2; h++) {
            int rl = wm * 32 + mi * 16 + g + h * 8;
            int crow = crows_s[rl];
            if (crow < 0) continue;
            float* Crow = C + (size_t)crow * ldc;
#pragma unroll
            for (int ni = 0; ni < 8; ni++) {
                int col = n0 + wn * 64 + ni * 8 + 2 * ct;
                float v0 = acc[mi][ni][2 * h + 0] + bias[col];
                float v1 = acc[mi][ni][2 * h + 1] + bias[col + 1];
                if (act == 1) {
                    v0 = 0.5f * v0 * (1.f + erff(v0 * 0.70710678118654752f));
                    v1 = 0.5f * v1 * (1.f + erff(v1 * 0.70710678118654752f));
                } else if (act == 2) {
                    v0 = v0 / (1.f + __expf(-v0));
                    v1 = v1 / (1.f + __expf(-v1));
                }
                *(float2*)&Crow[col] = make_float2(v0, v1);
            }
        }
    }
}

// ========== 3xTF32 split GEMM (fp32-accurate; dense A, row-major W) =========
__global__ void __launch_bounds__(256)
mm_split_kernel(const float* __restrict__ A,
                const float* __restrict__ W0, const float* __restrict__ W1,
                const float* __restrict__ W2,
                const float* __restrict__ bias0, const float* __restrict__ bias1,
                const float* __restrict__ bias2,
                const float* __restrict__ resid,
                float* __restrict__ Cbase,
                int K, int N)
{
    int z = blockIdx.z;
    int m0 = blockIdx.y * 128;
    int n0 = blockIdx.x * 128;
    const float* W = (z == 0) ? W0 : ((z == 1) ? W1 : W2);
    const float* bias = (z == 0) ? bias0 : ((z == 1) ? bias1 : bias2);
    float* C = Cbase + (size_t)z * TT * N;

    extern __shared__ float smf[];
    float* As = smf;
    float* Bs = smf + 2 * ASTG;
    uint32_t uA = smem_u32(As);
    uint32_t uB = smem_u32(Bs);

    int tid = threadIdx.x;

    auto load_stage = [&](int s, int k0) {
#pragma unroll
        for (int i = 0; i < 4; i++) {
            int chunk = tid + i * 256;
            int row = chunk >> 3;
            int kc = chunk & 7;
            uint32_t offA = (uint32_t)(s * ASTG + row * ALDP + kc * 4) * 4u;
            cp16(uA + offA, A + (size_t)(m0 + row) * K + k0 + kc * 4);
            int brow = chunk >> 5;
            int bc = chunk & 31;
            uint32_t offB = (uint32_t)(s * BSTG + brow * BLDN + bc * 4) * 4u;
            cp16(uB + offB, W + (size_t)(k0 + brow) * N + n0 + bc * 4);
        }
    };

    int NC = K >> 5;
    load_stage(0, 0); cp_commit();
    load_stage(1, 32); cp_commit();

    int w = tid >> 5, lane = tid & 31;
    int wm = w & 3, wn = w >> 2;
    int g = lane >> 2, ct = lane & 3;

    float acc[2][8][4];
#pragma unroll
    for (int mi = 0; mi < 2; mi++)
#pragma unroll
        for (int ni = 0; ni < 8; ni++)
#pragma unroll
            for (int j = 0; j < 4; j++) acc[mi][ni][j] = 0.f;

    for (int i = 0; i < NC; i++) {
        if (i + 1 < NC) cp_wait1(); else cp_wait0();
        __syncthreads();
        const float* Aw = As + (i & 1) * ASTG;
        const float* Bw = Bs + (i & 1) * BSTG;
#pragma unroll
        for (int ks = 0; ks < 4; ks++) {
            int kc = ks * 8 + ct;
            float ah[2][4], al[2][4];
#pragma unroll
            for (int mi = 0; mi < 2; mi++) {
                int rb = wm * 32 + mi * 16;
                float a0 = Aw[(rb + g) * ALDP + kc];
                float a1 = Aw[(rb + g + 8) * ALDP + kc];
                float a2 = Aw[(rb + g) * ALDP + kc + 4];
                float a3 = Aw[(rb + g + 8) * ALDP + kc + 4];
                ah[mi][0] = tf32_hi(a0); al[mi][0] = a0 - ah[mi][0];
                ah[mi][1] = tf32_hi(a1); al[mi][1] = a1 - ah[mi][1];
                ah[mi][2] = tf32_hi(a2); al[mi][2] = a2 - ah[mi][2];
                ah[mi][3] = tf32_hi(a3); al[mi][3] = a3 - ah[mi][3];
            }
            const float* Br0 = Bw + (size_t)kc * BLDN;
            const float* Br1 = Bw + (size_t)(kc + 4) * BLDN;
            float bh[8][2], bl[8][2];
#pragma unroll
            for (int ni = 0; ni < 8; ni++) {
                int nc = wn * 64 + ni * 8 + g;
                float b0 = Br0[nc];
                float b1 = Br1[nc];
                bh[ni][0] = tf32_hi(b0); bl[ni][0] = b0 - bh[ni][0];
                bh[ni][1] = tf32_hi(b1); bl[ni][1] = b1 - bh[ni][1];
            }
#pragma unroll
            for (int mi = 0; mi < 2; mi++)
#pragma unroll
                for (int ni = 0; ni < 8; ni++) {
                    mma_tf32(acc[mi][ni], ah[mi], bl[ni]);
                    mma_tf32(acc[mi][ni], al[mi], bh[ni]);
                    mma_tf32(acc[mi][ni], ah[mi], bh[ni]);
                }
        }
        __syncthreads();
        if (i + 2 < NC) { load_stage(i & 1, (i + 2) << 5); cp_commit(); }
    }

#pragma unroll
    for (int mi = 0; mi < 2; mi++) {
#pragma unroll
        for (int h = 0; h < 2; h++) {
            int m = m0 + wm * 32 + mi * 16 + g + h * 8;
            float* Crow = C + (size_t)m * N;
            const float* rrow = resid ? resid + (size_t)m * N : nullptr;
#pragma unroll
            for (int ni = 0; ni < 8; ni++) {
                int col = n0 + wn * 64 + ni * 8 + 2 * ct;
                float v0 = acc[mi][ni][2 * h + 0] + bias[col];
                float v1 = acc[mi][ni][2 * h + 1] + bias[col + 1];
                if (rrow) { v0 += rrow[col]; v1 += rrow[col + 1]; }
                *(float2*)&Crow[col] = make_float2(v0, v1);
            }
        }
    }
}

// ========== tf32-split mma flash attention ==========
// grid (SS/64, HH, B); 256 threads (8 warps: 4 over q-rows, 2 over cols)
#define QLD 68
#define ATTN_SMEM (4 * 64 * QLD * 4)   // Qs, Ks, Vt, Ps = 69632 bytes

__global__ void __launch_bounds__(256, 2)
attn_mma_kernel(const float* __restrict__ q,
                const float* __restrict__ k,
                const float* __restrict__ v,
                float* __restrict__ ctx)
{
    extern __shared__ float sm[];
    float* Qs = sm;                 // [64 q][64 dk] pad QLD
    float* Ks = sm + 64 * QLD;      // [64 key][64 dk]
    float* Vt = sm + 2 * 64 * QLD;  // [64 dk][64 key]
    float* Ps = sm + 3 * 64 * QLD;  // [64 q][64 key]
    __shared__ float redm[128], reds[128];

    int qt = blockIdx.x, h = blockIdx.y, b = blockIdx.z;
    int tid = threadIdx.x;
    int w = tid >> 5, lane = tid & 31;
    int wm = w & 3, wn = w >> 2;
    int g = lane >> 2, ct = lane & 3;
    int r0 = wm * 16 + g, r1 = r0 + 8;

    size_t base = ((size_t)b * SS) * DD + (size_t)h * DK;
    const float* qb = q + base + (size_t)qt * 64 * DD;
    const float* kb = k + base;
    const float* vb = v + base;

    uint32_t uQ = smem_u32(Qs), uK = smem_u32(Ks);

    // load Q once (cp.async)
#pragma unroll
    for (int i = 0; i < 4; i++) {
        int ch = tid + i * 256;
        int row = ch >> 4, c4 = ch & 15;
        cp16(uQ + (uint32_t)(row * QLD + c4 * 4) * 4, qb + (size_t)row * DD + c4 * 4);
    }
    cp_commit();

    float oacc[4][4];
#pragma unroll
    for (int ni = 0; ni < 4; ni++)
#pragma unroll
        for (int j = 0; j < 4; j++) oacc[ni][j] = 0.f;
    float mrun0 = -1e30f, mrun1 = -1e30f, lrun0 = 0.f, lrun1 = 0.f;

    for (int t = 0; t < SS / 64; t++) {
        int k0t = t * 64;
        __syncthreads();   // Ks/Vt free (prev PV done)
#pragma unroll
        for (int i = 0; i < 4; i++) {
            int ch = tid + i * 256;
            int row = ch >> 4, c4 = ch & 15;
            cp16(uK + (uint32_t)(row * QLD + c4 * 4) * 4,
                 kb + (size_t)(k0t + row) * DD + c4 * 4);
        }
        cp_commit();
        // V transposed (scalar)
#pragma unroll
        for (int i = 0; i < 16; i++) {
            int idx = tid + i * 256;
            int key = idx >> 6, d = idx & 63;
            Vt[d * QLD + key] = vb[(size_t)(k0t + key) * DD + d];
        }
        cp_wait0();
        __syncthreads();

        // ---- S = Q @ K^T (3xTF32 split) ----
        float sacc[4][4];
#pragma unroll
        for (int ni = 0; ni < 4; ni++)
#pragma unroll
            for (int j = 0; j < 4; j++) sacc[ni][j] = 0.f;
#pragma unroll
        for (int ks = 0; ks < 8; ks++) {
            int kc = ks * 8 + ct;
            float a0 = Qs[r0 * QLD + kc], a1 = Qs[r1 * QLD + kc];
            float a2 = Qs[r0 * QLD + kc + 4], a3 = Qs[r1 * QLD + kc + 4];
            float ah[4], al[4];
            ah[0] = tf32_hi(a0); al[0] = a0 - ah[0];
            ah[1] = tf32_hi(a1); al[1] = a1 - ah[1];
            ah[2] = tf32_hi(a2); al[2] = a2 - ah[2];
            ah[3] = tf32_hi(a3); al[3] = a3 - ah[3];
#pragma unroll
            for (int ni = 0; ni < 4; ni++) {
                int nb = wn * 32 + ni * 8;
                float b0 = Ks[(nb + g) * QLD + kc];
                float b1 = Ks[(nb + g) * QLD + kc + 4];
                float bh[2], bl[2];
                bh[0] = tf32_hi(b0); bl[0] = b0 - bh[0];
                bh[1] = tf32_hi(b1); bl[1] = b1 - bh[1];
                mma_tf32(sacc[ni], ah, bl);
                mma_tf32(sacc[ni], al, bh);
                mma_tf32(sacc[ni], ah, bh);
            }
        }
#pragma unroll
        for (int ni = 0; ni < 4; ni++)
#pragma unroll
            for (int j = 0; j < 4; j++) sacc[ni][j] *= 0.125f;

        // ---- online softmax ----
        float mx0 = -1e30f, mx1 = -1e30f;
#pragma unroll
        for (int ni = 0; ni < 4; ni++) {
            mx0 = fmaxf(mx0, fmaxf(sacc[ni][0], sacc[ni][1]));
            mx1 = fmaxf(mx1, fmaxf(sacc[ni][2], sacc[ni][3]));
        }
        mx0 = fmaxf(mx0, __shfl_xor_sync(~0u, mx0, 1));
        mx0 = fmaxf(mx0, __shfl_xor_sync(~0u, mx0, 2));
        mx1 = fmaxf(mx1, __shfl_xor_sync(~0u, mx1, 1));
        mx1 = fmaxf(mx1, __shfl_xor_sync(~0u, mx1, 2));
        if (ct == 0) { redm[wn * 64 + r0] = mx0; redm[wn * 64 + r1] = mx1; }
        __syncthreads();
        float mn0 = fmaxf(mrun0, fmaxf(redm[r0], redm[64 + r0]));
        float mn1 = fmaxf(mrun1, fmaxf(redm[r1], redm[64 + r1]));
        float c0 = fexp(mrun0 - mn0), c1 = fexp(mrun1 - mn1);
        mrun0 = mn0; mrun1 = mn1;
        float sum0 = 0.f, sum1 = 0.f;
#pragma unroll
        for (int ni = 0; ni < 4; ni++) {
            float p00 = fexp(sacc[ni][0] - mn0), p01 = fexp(sacc[ni][1] - mn0);
            float p10 = fexp(sacc[ni][2] - mn1), p11 = fexp(sacc[ni][3] - mn1);
            sum0 += p00 + p01; sum1 += p10 + p11;
            int col = wn * 32 + ni * 8 + 2 * ct;
            *(float2*)&Ps[r0 * QLD + col] = make_float2(p00, p01);
            *(float2*)&Ps[r1 * QLD + col] = make_float2(p10, p11);
        }
        sum0 += __shfl_xor_sync(~0u, sum0, 1);
        sum0 += __shfl_xor_sync(~0u, sum0, 2);
        sum1 += __shfl_xor_sync(~0u, sum1, 1);
        sum1 += __shfl_xor_sync(~0u, sum1, 2);
        if (ct == 0) { reds[wn * 64 + r0] = sum0; reds[wn * 64 + r1] = sum1; }
        __syncthreads();
        lrun0 = lrun0 * c0 + reds[r0] + reds[64 + r0];
        lrun1 = lrun1 * c1 + reds[r1] + reds[64 + r1];
#pragma unroll
        for (int ni = 0; ni < 4; ni++) {
            oacc[ni][0] *= c0; oacc[ni][1] *= c0;
            oacc[ni][2] *= c1; oacc[ni][3] *= c1;
        }

        // ---- O += P @ V (3xTF32 split) ----
#pragma unroll
        for (int ks = 0; ks < 8; ks++) {
            int kc = ks * 8 + ct;
            float a0 = Ps[r0 * QLD + kc], a1 = Ps[r1 * QLD + kc];
            float a2 = Ps[r0 * QLD + kc + 4], a3 = Ps[r1 * QLD + kc + 4];
            float ah[4], al[4];
            ah[0] = tf32_hi(a0); al[0] = a0 - ah[0];
            ah[1] = tf32_hi(a1); al[1] = a1 - ah[1];
            ah[2] = tf32_hi(a2); al[2] = a2 - ah[2];
            ah[3] = tf32_hi(a3); al[3] = a3 - ah[3];
#pragma unroll
            for (int ni = 0; ni < 4; ni++) {
                int nb = wn * 32 + ni * 8;
                float b0 = Vt[(nb + g) * QLD + kc];
                float b1 = Vt[(nb + g) * QLD + kc + 4];
                float bh[2], bl[2];
                bh[0] = tf32_hi(b0); bl[0] = b0 - bh[0];
                bh[1] = tf32_hi(b1); bl[1] = b1 - bh[1];
                mma_tf32(oacc[ni], ah, bl);
                mma_tf32(oacc[ni], al, bh);
                mma_tf32(oacc[ni], ah, bh);
            }
        }
    }

    float inv0 = 1.f / lrun0, inv1 = 1.f / lrun1;
    float* cb = ctx + base + (size_t)qt * 64 * DD;
#pragma unroll
    for (int ni = 0; ni < 4; ni++) {
        int col = wn * 32 + ni * 8 + 2 * ct;
        *(float2*)&cb[(size_t)r0 * DD + col] =
            make_float2(oacc[ni][0] * inv0, oacc[ni][1] * inv0);
        *(float2*)&cb[(size_t)r1 * DD + col] =
            make_float2(oacc[ni][2] * inv1, oacc[ni][3] * inv1);
    }
}

// ---------------- layernorm ----------------
__global__ void ln_kernel(const float* __restrict__ in,
                          const float* __restrict__ gam,
                          const float* __restrict__ bet,
                          float* __restrict__ out)
{
    __shared__ float ssum[8], ssum2[8];
    __shared__ float smean, srstd;
    int t = blockIdx.x;
    const float4* r = (const float4*)(in + (size_t)t * DD);
    float4 vv = r[threadIdx.x];
    float s = vv.x + vv.y + vv.z + vv.w;
    float s2 = vv.x * vv.x + vv.y * vv.y + vv.z * vv.z + vv.w * vv.w;
    int lane = threadIdx.x & 31, w = threadIdx.x >> 5;
#pragma unroll
    for (int o = 16; o; o >>= 1) {
        s += __shfl_xor_sync(~0u, s, o);
        s2 += __shfl_xor_sync(~0u, s2, o);
    }
    if (!lane) { ssum[w] = s; ssum2[w] = s2; }
    __syncthreads();
    if (threadIdx.x == 0) {
        float a = 0.f, bb = 0.f;
#pragma unroll
        for (int i = 0; i < 8; i++) { a += ssum[i]; bb += ssum2[i]; }
        float mean = a * (1.f / DD);
        float var = bb * (1.f / DD) - mean * mean;
        smean = mean; srstd = rsqrtf(var + 1e-5f);
    }
    __syncthreads();
    float4 g4 = ((const float4*)gam)[threadIdx.x];
    float4 b4 = ((const float4*)bet)[threadIdx.x];
    float m = smean, rs = srstd;
    float4 o4;
    o4.x = (vv.x - m) * rs * g4.x + b4.x;
    o4.y = (vv.y - m) * rs * g4.y + b4.y;
    o4.z = (vv.z - m) * rs * g4.z + b4.z;
    o4.w = (vv.w - m) * rs * g4.w + b4.w;
    ((float4*)(out + (size_t)t * DD))[threadIdx.x] = o4;
}

// ---------------- gate ----------------
__global__ void zero_counts_kernel() {
    if (threadIdx.x < EE) g_counts[threadIdx.x] = 0;
}

__global__ void gate_kernel(const float* __restrict__ x1,
                            const float* __restrict__ gw,
                            const float* __restrict__ gb)
{
    int t = blockIdx.x * (blockDim.x / 32) + (threadIdx.x >> 5);
    int lane = threadIdx.x & 31;
    float acc[EE] = {};
    const float* xr = x1 + (size_t)t * DD;
    for (int d = lane; d < DD; d += 32) {
        float xv = xr[d];
        const float* grow = gw + (size_t)d * EE;
#pragma unroll
        for (int e = 0; e < EE; e++) acc[e] += xv * grow[e];
    }
#pragma unroll
    for (int e = 0; e < EE; e++)
#pragma unroll
        for (int o = 16; o; o >>= 1) acc[e] += __shfl_xor_sync(~0u, acc[e], o);
    if (lane == 0) {
#pragma unroll
        for (int e = 0; e < EE; e++) acc[e] += gb[e];
        float best = -1e30f; int bi = 0;
#pragma unroll
        for (int e = 0; e < EE; e++)
            if (acc[e] > best) { best = acc[e]; bi = e; }
        float best2 = -1e30f; int bi2 = 0;
#pragma unroll
        for (int e = 0; e < EE; e++)
            if (e != bi && acc[e] > best2) { best2 = acc[e]; bi2 = e; }
        float w0 = 1.f / (1.f + __expf(best2 - best));
        g_gatew[2 * t] = w0;
        g_gatew[2 * t + 1] = 1.f - w0;
        int p0 = atomicAdd(&g_counts[bi], 1);
        g_list[bi * TT + p0] = 2 * t;
        int p1 = atomicAdd(&g_counts[bi2], 1);
        g_list[bi2 * TT + p1] = 2 * t + 1;
    }
}

// ---------------- combine experts + residual + LN3 -> out ----------------
__global__ void combine_ln_kernel(const float* __restrict__ x1,
                                  const float* __restrict__ gam,
                                  const float* __restrict__ bet,
                                  float* __restrict__ out)
{
    __shared__ float ssum[8], ssum2[8];
    __shared__ float smean, srstd;
    int t = blockIdx.x;
    float w0 = g_gatew[2 * t], w1 = g_gatew[2 * t + 1];
    const float4* xr = (const float4*)(x1 + (size_t)t * DD);
    const float4* y0 = (const float4*)(g_y + (size_t)(2 * t) * DD);
    const float4* y1 = (const float4*)(g_y + (size_t)(2 * t + 1) * DD);
    float4 a = xr[threadIdx.x];
    float4 c0 = y0[threadIdx.x];
    float4 c1 = y1[threadIdx.x];
    float4 vv;
    vv.x = a.x + w0 * c0.x + w1 * c1.x;
    vv.y = a.y + w0 * c0.y + w1 * c1.y;
    vv.z = a.z + w0 * c0.z + w1 * c1.z;
    vv.w = a.w + w0 * c0.w + w1 * c1.w;
    float s = vv.x + vv.y + vv.z + vv.w;
    float s2 = vv.x * vv.x + vv.y * vv.y + vv.z * vv.z + vv.w * vv.w;
    int lane = threadIdx.x & 31, w = threadIdx.x >> 5;
#pragma unroll
    for (int o = 16; o; o >>= 1) {
        s += __shfl_xor_sync(~0u, s, o);
        s2 += __shfl_xor_sync(~0u, s2, o);
    }
    if (!lane) { ssum[w] = s; ssum2[w] = s2; }
    __syncthreads();
    if (threadIdx.x == 0) {
        float aa = 0.f, bb = 0.f;
#pragma unroll
        for (int i = 0; i < 8; i++) { aa += ssum[i]; bb += ssum2[i]; }
        float mean = aa * (1.f / DD);
        float var = bb * (1.f / DD) - mean * mean;
        smean = mean; srstd = rsqrtf(var + 1e-5f);
    }
    __syncthreads();
    float4 g4 = ((const float4*)gam)[threadIdx.x];
    float4 b4 = ((const float4*)bet)[threadIdx.x];
    float m = smean, rs = srstd;
    float4 o4;
    o4.x = (vv.x - m) * rs * g4.x + b4.x;
    o4.y = (vv.y - m) * rs * g4.y + b4.y;
    o4.z = (vv.z - m) * rs * g4.z + b4.z;
    o4.w = (vv.w - m) * rs * g4.w + b4.w;
    ((float4*)(out + (size_t)t * DD))[threadIdx.x] = o4;
}

// ---------------- launch ----------------
extern "C" void kernel_launch(void* const* d_in, const int* in_sizes, int n_in,
                              void* d_out, int out_size)
{
    const float* x    = (const float*)d_in[0];
    const float* Wq   = (const float*)d_in[1];
    const float* bq   = (const float*)d_in[2];
    const float* Wk   = (const float*)d_in[3];
    const float* bk   = (const float*)d_in[4];
    const float* Wv   = (const float*)d_in[5];
    const float* bv   = (const float*)d_in[6];
    const float* Wo   = (const float*)d_in[7];
    const float* bo   = (const float*)d_in[8];
    const float* ln1g = (const float*)d_in[9];
    const float* ln1b = (const float*)d_in[10];
    const float* gw   = (const float*)d_in[11];
    const float* gb   = (const float*)d_in[12];
    const float* W1   = (const float*)d_in[13];
    const float* b1   = (const float*)d_in[14];
    const float* W2   = (const float*)d_in[15];
    const float* b2   = (const float*)d_in[16];
    const float* ln3g = (const float*)d_in[17];
    const float* ln3b = (const float*)d_in[18];
    float* out = (float*)d_out;

    static int attr_set = 0;
    if (!attr_set) {
        cudaFuncSetAttribute(mm_mma_kernel, cudaFuncAttributeMaxDynamicSharedMemorySize, MMA_SMEM);
        cudaFuncSetAttribute(mm_split_kernel, cudaFuncAttributeMaxDynamicSharedMemorySize, MMA_SMEM);
        cudaFuncSetAttribute(attn_mma_kernel, cudaFuncAttributeMaxDynamicSharedMemorySize, ATTN_SMEM);
        attr_set = 1;
    }

    float *pqkv, *pctx, *pres1, *px1, *pact, *py;
    int *pcounts, *plist;
    cudaGetSymbolAddress((void**)&pqkv, g_qkv);
    cudaGetSymbolAddress((void**)&pctx, g_ctx);
    cudaGetSymbolAddress((void**)&pres1, g_res1);
    cudaGetSymbolAddress((void**)&px1, g_x1);
    cudaGetSymbolAddress((void**)&pact, g_act);
    cudaGetSymbolAddress((void**)&py, g_y);
    cudaGetSymbolAddress((void**)&pcounts, g_counts);
    cudaGetSymbolAddress((void**)&plist, g_list);

    // QKV projections (3xTF32 split, row-major W, no transposes)
    mm_split_kernel<<<dim3(DD / 128, TT / 128, 3), 256, MMA_SMEM>>>(
        x, Wq, Wk, Wv, bq, bk, bv, nullptr, pqkv, DD, DD);

    // attention (tf32-split mma flash)
    attn_mma_kernel<<<dim3(SS / 64, HH, 2), 256, ATTN_SMEM>>>(
        pqkv, pqkv + (size_t)TT * DD, pqkv + 2u * TT * DD, pctx);

    // O projection + residual
    mm_split_kernel<<<dim3(DD / 128, TT / 128, 1), 256, MMA_SMEM>>>(
        pctx, Wo, Wo, Wo, bo, bo, bo, x, pres1, DD, DD);

    // LN1
    ln_kernel<<<TT, 256>>>(pres1, ln1g, ln1b, px1);

    // gate + dispatch
    zero_counts_kernel<<<1, 32>>>();
    gate_kernel<<<TT / 8, 256>>>(px1, gw, gb);

    // FFN1 (tf32 mma, gathered, row-major W1)
    mm_mma_kernel<<<dim3(FF / 128, TT / 128, EE), 256, MMA_SMEM>>>(
        px1, W1, b1, pact, TT, DD, FF, DD, FF, plist, pcounts, 1, 3);

    // FFN2 (tf32 mma, gathered, row-major W2)
    mm_mma_kernel<<<dim3(DD / 128, TT / 128, EE), 256, MMA_SMEM>>>(
        pact, W2, b2, py, TT, FF, DD, FF, DD, plist, pcounts, 0, 0);

    // combine + residual + LN3 -> out
    combine_ln_kernel<<<TT, 256>>>(px1, ln3g, ln3b, out);
}

// round 7
// speedup vs baseline: 5.1887x; 1.5716x over previous
#include <cuda_runtime.h>
#include <cuda_fp16.h>
#include <math.h>
#include <stdint.h>

#define TT 4096
#define DD 1024
#define FF 4096
#define EE 8
#define SS 2048
#define HH 16
#define DK 64
#define DP (DD/2)   // 512 pairs

// ---------------- scratch ----------------
__device__ uint32_t g_xh[TT * DP], g_xl[TT * DP];            // x packed (pairs along D)
__device__ uint32_t g_wqkvh[3u * DP * DD], g_wqkvl[3u * DP * DD]; // Wq/Wk/Wv [z][K/2][N]
__device__ uint32_t g_woh[DP * DD], g_wol[DP * DD];
__device__ uint32_t g_qkh[2u * TT * DP], g_qkl[2u * TT * DP]; // Q,K packed [2][T][D/2]
__device__ float    g_v[TT * DD];
__device__ uint32_t g_vh[(TT / 2) * DD], g_vl[(TT / 2) * DD]; // V packed (pairs along token)
__device__ uint32_t g_cth[TT * DP], g_ctl[TT * DP];           // ctx packed
__device__ float    g_res1[TT * DD];
__device__ float    g_x1[TT * DD];
__device__ uint32_t g_x1h[TT * DP];                           // x1 fp16 (plain)
__device__ uint32_t g_w1h[(size_t)EE * DP * FF];              // W1 fp16 [E][D/2][F]
__device__ uint32_t g_w2h[(size_t)EE * (FF / 2) * DD];        // W2 fp16 [E][F/2][D]
__device__ uint32_t g_acth[2u * TT * (FF / 2)];               // act fp16 packed
__device__ float    g_y[2u * TT * DD];
__device__ float    g_gatew[2 * TT];
__device__ int      g_counts[EE];
__device__ int      g_list[EE * TT];
__device__ float    g_bqkv[3 * DD];

// ---------------- helpers ----------------
__device__ __forceinline__ uint32_t smem_u32(const void* p) {
    uint32_t a;
    asm("{ .reg .u64 t; cvta.to.shared.u64 t, %1; cvt.u32.u64 %0, t; }" : "=r"(a) : "l"(p));
    return a;
}
__device__ __forceinline__ void cp16(uint32_t dst, const void* src) {
    asm volatile("cp.async.cg.shared.global [%0], [%1], 16;" :: "r"(dst), "l"(src));
}
__device__ __forceinline__ void cp16z(uint32_t dst, const void* src, int sz) {
    asm volatile("cp.async.cg.shared.global [%0], [%1], 16, %2;" :: "r"(dst), "l"(src), "r"(sz));
}
__device__ __forceinline__ void cp_commit() { asm volatile("cp.async.commit_group;"); }
__device__ __forceinline__ void cp_wait1() { asm volatile("cp.async.wait_group 1;" ::: "memory"); }
__device__ __forceinline__ void cp_wait0() { asm volatile("cp.async.wait_group 0;" ::: "memory"); }

__device__ __forceinline__ void mma_f16(float* d, const uint32_t* a, const uint32_t* b) {
    asm volatile(
        "mma.sync.aligned.m16n8k16.row.col.f32.f16.f16.f32 "
        "{%0,%1,%2,%3}, {%4,%5,%6,%7}, {%8,%9}, {%0,%1,%2,%3};"
        : "+f"(d[0]), "+f"(d[1]), "+f"(d[2]), "+f"(d[3])
        : "r"(a[0]), "r"(a[1]), "r"(a[2]), "r"(a[3]), "r"(b[0]), "r"(b[1]));
}
__device__ __forceinline__ uint32_t packh2(float a, float b) {
    __half2 h = __floats2half2_rn(a, b);
    return *reinterpret_cast<uint32_t*>(&h);
}
__device__ __forceinline__ void split2(float a, float b, uint32_t& hi, uint32_t& lo) {
    __half2 h = __floats2half2_rn(a, b);
    float2 f = __half22float2(h);
    __half2 l = __floats2half2_rn(a - f.x, b - f.y);
    hi = *reinterpret_cast<uint32_t*>(&h);
    lo = *reinterpret_cast<uint32_t*>(&l);
}
// fast exp (x<=0), FMA-only
__device__ __forceinline__ float fexp(float x) {
    float t = fmaxf(x * 1.4426950408889634f, -126.0f);
    float fl = floorf(t);
    float f = t - fl;
    float p = 1.53998500e-4f;
    p = fmaf(p, f, 1.33335581e-3f);
    p = fmaf(p, f, 9.61817007e-3f);
    p = fmaf(p, f, 5.55041087e-2f);
    p = fmaf(p, f, 2.40226507e-1f);
    p = fmaf(p, f, 6.93147182e-1f);
    p = fmaf(p, f, 1.0f);
    return __int_as_float(__float_as_int(p) + (((int)fl) << 23));
}

// ---------------- pack kernels ----------------
// pairs along rows: out[r][c] = pack(in[2r][c], in[2r+1][c]); grid(C/1024, Rh), 256 thr
__global__ void pack_rows_kernel(const float* __restrict__ in, uint32_t* __restrict__ oh,
                                 uint32_t* __restrict__ ol, int C)
{
    int r = blockIdx.y;
    int c = blockIdx.x * 1024 + threadIdx.x * 4;
    const float* r0 = in + (size_t)(2 * r) * C + c;
    const float* r1 = r0 + C;
    float4 a = *(const float4*)r0;
    float4 b = *(const float4*)r1;
    uint32_t* ohp = oh + (size_t)r * C + c;
    if (ol) {
        uint32_t h, l;
        uint32_t* olp = ol + (size_t)r * C + c;
        split2(a.x, b.x, h, l); ohp[0] = h; olp[0] = l;
        split2(a.y, b.y, h, l); ohp[1] = h; olp[1] = l;
        split2(a.z, b.z, h, l); ohp[2] = h; olp[2] = l;
        split2(a.w, b.w, h, l); ohp[3] = h; olp[3] = l;
    } else {
        ohp[0] = packh2(a.x, b.x);
        ohp[1] = packh2(a.y, b.y);
        ohp[2] = packh2(a.z, b.z);
        ohp[3] = packh2(a.w, b.w);
    }
}

// pairs along cols: out[r][p] = pack(in[r][2p], in[r][2p+1]); C=1024 fixed; grid(1, R)
__global__ void pack_cols_kernel(const float* __restrict__ in, uint32_t* __restrict__ oh,
                                 uint32_t* __restrict__ ol)
{
    int r = blockIdx.x;
    int c = threadIdx.x * 4;
    float4 a = *(const float4*)(in + (size_t)r * DD + c);
    uint32_t h0, l0, h1, l1;
    split2(a.x, a.y, h0, l0);
    split2(a.z, a.w, h1, l1);
    oh[(size_t)r * DP + (c >> 1)] = h0;
    oh[(size_t)r * DP + (c >> 1) + 1] = h1;
    ol[(size_t)r * DP + (c >> 1)] = l0;
    ol[(size_t)r * DP + (c >> 1) + 1] = l1;
}

__global__ void concat_bias_kernel(const float* bq, const float* bk, const float* bv,
                                   float* out)
{
    int i = blockIdx.x * 256 + threadIdx.x;
    if (i < DD) { out[i] = bq[i]; out[DD + i] = bk[i]; out[2 * DD + i] = bv[i]; }
}

// ========== fp16 2-way-split GEMM (fp32-faithful): QKV + O ==========
#define AP2 20
#define ASTG2 (128 * AP2)   // u32 per A plane per stage
#define BP2 136
#define BSTG2 (16 * BP2)
#define SPLIT_SMEM ((2 * 2 * ASTG2 + 2 * 2 * BSTG2) * 4)   // 75776 B

__global__ void __launch_bounds__(256)
mm_half_split(const uint32_t* __restrict__ Ah, const uint32_t* __restrict__ Al,
              const uint32_t* __restrict__ BhB, const uint32_t* __restrict__ BlB, // [Z][K/2][N]
              const float* __restrict__ biasB,   // [Z][N]
              const float* __restrict__ resid,
              uint32_t* __restrict__ OHB, uint32_t* __restrict__ OLB, // [z][M][N/2] for z<fp32z
              float* __restrict__ OF,            // fp32 out for z==fp32z
              int K, int N, int fp32z)
{
    int z = blockIdx.z;
    int m0 = blockIdx.y * 128;
    int n0 = blockIdx.x * 128;
    int Kp = K >> 1;
    const uint32_t* Bh = BhB + (size_t)z * Kp * N;
    const uint32_t* Bl = BlB + (size_t)z * Kp * N;
    const float* bias = biasB + (size_t)z * N;

    extern __shared__ uint32_t smu[];
    uint32_t* sAh = smu;
    uint32_t* sAl = smu + 2 * ASTG2;
    uint32_t* sBh = smu + 4 * ASTG2;
    uint32_t* sBl = smu + 4 * ASTG2 + 2 * BSTG2;
    uint32_t uAh = smem_u32(sAh), uAl = smem_u32(sAl);
    uint32_t uBh = smem_u32(sBh), uBl = smem_u32(sBl);

    int tid = threadIdx.x;

    auto load_stage = [&](int s, int kp0) {
#pragma unroll
        for (int i = 0; i < 8; i++) {
            int c = (tid + (i & 1) * 256) & 511;
            if (i < 4) {
                int row = c >> 2, seg = c & 3;
                const uint32_t* g = (i < 2) ? Ah : Al;
                uint32_t u = (i < 2) ? uAh : uAl;
                cp16(u + (uint32_t)(s * ASTG2 + row * AP2 + seg * 4) * 4,
                     g + (size_t)(m0 + row) * Kp + kp0 + seg * 4);
            } else {
                int prow = c >> 5, seg = c & 31;
                const uint32_t* g = (i < 6) ? Bh : Bl;
                uint32_t u = (i < 6) ? uBh : uBl;
                cp16(u + (uint32_t)(s * BSTG2 + prow * BP2 + seg * 4) * 4,
                     g + (size_t)(kp0 + prow) * N + n0 + seg * 4);
            }
        }
    };

    int NC = K >> 5;
    load_stage(0, 0); cp_commit();
    load_stage(1, 16); cp_commit();

    int w = tid >> 5, lane = tid & 31;
    int wm = w & 3, wn = w >> 2;
    int g = lane >> 2, ct = lane & 3;

    float acc[2][8][4];
#pragma unroll
    for (int mi = 0; mi < 2; mi++)
#pragma unroll
        for (int ni = 0; ni < 8; ni++)
#pragma unroll
            for (int j = 0; j < 4; j++) acc[mi][ni][j] = 0.f;

    for (int i = 0; i < NC; i++) {
        if (i + 1 < NC) cp_wait1(); else cp_wait0();
        __syncthreads();
        const uint32_t* Ahw = sAh + (i & 1) * ASTG2;
        const uint32_t* Alw = sAl + (i & 1) * ASTG2;
        const uint32_t* Bhw = sBh + (i & 1) * BSTG2;
        const uint32_t* Blw = sBl + (i & 1) * BSTG2;
#pragma unroll
        for (int ks = 0; ks < 2; ks++) {
            int kb = ks * 8;
            uint32_t ah[2][4], al[2][4];
#pragma unroll
            for (int mi = 0; mi < 2; mi++) {
                int rb = wm * 32 + mi * 16;
                ah[mi][0] = Ahw[(rb + g) * AP2 + kb + ct];
                ah[mi][1] = Ahw[(rb + g + 8) * AP2 + kb + ct];
                ah[mi][2] = Ahw[(rb + g) * AP2 + kb + ct + 4];
                ah[mi][3] = Ahw[(rb + g + 8) * AP2 + kb + ct + 4];
                al[mi][0] = Alw[(rb + g) * AP2 + kb + ct];
                al[mi][1] = Alw[(rb + g + 8) * AP2 + kb + ct];
                al[mi][2] = Alw[(rb + g) * AP2 + kb + ct + 4];
                al[mi][3] = Alw[(rb + g + 8) * AP2 + kb + ct + 4];
            }
#pragma unroll
            for (int ni = 0; ni < 8; ni++) {
                int n = wn * 64 + ni * 8 + g;
                uint32_t bh[2] = { Bhw[(kb + ct) * BP2 + n], Bhw[(kb + ct + 4) * BP2 + n] };
                uint32_t bl[2] = { Blw[(kb + ct) * BP2 + n], Blw[(kb + ct + 4) * BP2 + n] };
#pragma unroll
                for (int mi = 0; mi < 2; mi++) {
                    mma_f16(acc[mi][ni], ah[mi], bh);
                    mma_f16(acc[mi][ni], ah[mi], bl);
                    mma_f16(acc[mi][ni], al[mi], bh);
                }
            }
        }
        __syncthreads();
        if (i + 2 < NC) { load_stage(i & 1, (i + 2) * 16); cp_commit(); }
    }

    bool fp32o = (z == fp32z);
#pragma unroll
    for (int mi = 0; mi < 2; mi++) {
#pragma unroll
        for (int h = 0; h < 2; h++) {
            int m = m0 + wm * 32 + mi * 16 + g + h * 8;
#pragma unroll
            for (int ni = 0; ni < 8; ni++) {
                int col = n0 + wn * 64 + ni * 8 + 2 * ct;
                float v0 = acc[mi][ni][2 * h + 0] + bias[col];
                float v1 = acc[mi][ni][2 * h + 1] + bias[col + 1];
                if (fp32o) {
                    if (resid) {
                        v0 += resid[(size_t)m * N + col];
                        v1 += resid[(size_t)m * N + col + 1];
                    }
                    *(float2*)&OF[(size_t)m * N + col] = make_float2(v0, v1);
                } else {
                    uint32_t hh, ll;
                    split2(v0, v1, hh, ll);
                    size_t o = (size_t)z * TT * (N >> 1) + (size_t)m * (N >> 1) + (col >> 1);
                    OHB[o] = hh; OLB[o] = ll;
                }
            }
        }
    }
}

// ========== plain fp16 GEMM (gathered A) for MoE FFN ==========
#define PLAIN_SMEM ((2 * ASTG2 + 2 * BSTG2) * 4)   // 37888 B

__global__ void __launch_bounds__(256)
mm_half_plain(const uint32_t* __restrict__ Ah,      // [rows][K/2]
              const uint32_t* __restrict__ WhB,     // [E][K/2][N]
              const float* __restrict__ biasB,      // [E][N]
              uint32_t* __restrict__ OH,            // packed out [rows][N/2] (FFN1)
              float* __restrict__ OF,               // fp32 out (FFN2)
              int K, int N,
              const int* __restrict__ listB, const int* __restrict__ counts,
              int a_shift, int actmode)
{
    int e = blockIdx.z;
    const int* list = listB + e * TT;
    int Me = counts[e];
    int m0 = blockIdx.y * 128;
    if (m0 >= Me) return;
    int n0 = blockIdx.x * 128;
    int Kp = K >> 1;
    const uint32_t* Wh = WhB + (size_t)e * Kp * N;
    const float* bias = biasB + (size_t)e * N;

    extern __shared__ uint32_t smu[];
    uint32_t* sAh = smu;
    uint32_t* sBh = smu + 2 * ASTG2;
    uint32_t uAh = smem_u32(sAh), uBh = smem_u32(sBh);

    __shared__ int rows_s[128];
    __shared__ int crows_s[128];
    int tid = threadIdx.x;
    if (tid < 128) {
        int m = m0 + tid;
        int r = -1, cr = -1;
        if (m < Me) { int ent = list[m]; r = ent >> a_shift; cr = ent; }
        rows_s[tid] = r; crows_s[tid] = cr;
    }
    __syncthreads();

    auto load_stage = [&](int s, int kp0) {
#pragma unroll
        for (int i = 0; i < 4; i++) {
            int c = (tid + (i & 1) * 256) & 511;
            if (i < 2) {
                int row = c >> 2, seg = c & 3;
                int ar = rows_s[row];
                const uint32_t* src = (ar >= 0) ? Ah + (size_t)ar * Kp + kp0 + seg * 4 : Ah;
                cp16z(uAh + (uint32_t)(s * ASTG2 + row * AP2 + seg * 4) * 4, src,
                      (ar >= 0) ? 16 : 0);
            } else {
                int prow = c >> 5, seg = c & 31;
                cp16(uBh + (uint32_t)(s * BSTG2 + prow * BP2 + seg * 4) * 4,
                     Wh + (size_t)(kp0 + prow) * N + n0 + seg * 4);
            }
        }
    };

    int NC = K >> 5;
    load_stage(0, 0); cp_commit();
    load_stage(1, 16); cp_commit();

    int w = tid >> 5, lane = tid & 31;
    int wm = w & 3, wn = w >> 2;
    int g = lane >> 2, ct = lane & 3;

    float acc[2][8][4];
#pragma unroll
    for (int mi = 0; mi < 2; mi++)
#pragma unroll
        for (int ni = 0; ni < 8; ni++)
#pragma unroll
            for (int j = 0; j < 4; j++) acc[mi][ni][j] = 0.f;

    for (int i = 0; i < NC; i++) {
        if (i + 1 < NC) cp_wait1(); else cp_wait0();
        __syncthreads();
        const uint32_t* Ahw = sAh + (i & 1) * ASTG2;
        const uint32_t* Bhw = sBh + (i & 1) * BSTG2;
#pragma unroll
        for (int ks = 0; ks < 2; ks++) {
            int kb = ks * 8;
            uint32_t ah[2][4];
#pragma unroll
            for (int mi = 0; mi < 2; mi++) {
                int rb = wm * 32 + mi * 16;
                ah[mi][0] = Ahw[(rb + g) * AP2 + kb + ct];
                ah[mi][1] = Ahw[(rb + g + 8) * AP2 + kb + ct];
                ah[mi][2] = Ahw[(rb + g) * AP2 + kb + ct + 4];
                ah[mi][3] = Ahw[(rb + g + 8) * AP2 + kb + ct + 4];
            }
#pragma unroll
            for (int ni = 0; ni < 8; ni++) {
                int n = wn * 64 + ni * 8 + g;
                uint32_t bh[2] = { Bhw[(kb + ct) * BP2 + n], Bhw[(kb + ct + 4) * BP2 + n] };
#pragma unroll
                for (int mi = 0; mi < 2; mi++)
                    mma_f16(acc[mi][ni], ah[mi], bh);
            }
        }
        __syncthreads();
        if (i + 2 < NC) { load_stage(i & 1, (i + 2) * 16); cp_commit(); }
    }

    int act = (actmode == 3) ? ((e & 1) ? 2 : 1) : actmode;
#pragma unroll
    for (int mi = 0; mi < 2; mi++) {
#pragma unroll
        for (int h = 0; h < 2; h++) {
            int rl = wm * 32 + mi * 16 + g + h * 8;
            int crow = crows_s[rl];
            if (crow < 0) continue;
#pragma unroll
            for (int ni = 0; ni < 8; ni++) {
                int col = n0 + wn * 64 + ni * 8 + 2 * ct;
                float v0 = acc[mi][ni][2 * h + 0] + bias[col];
                float v1 = acc[mi][ni][2 * h + 1] + bias[col + 1];
                if (act == 1) {
                    v0 = 0.5f * v0 * (1.f + erff(v0 * 0.70710678118654752f));
                    v1 = 0.5f * v1 * (1.f + erff(v1 * 0.70710678118654752f));
                } else if (act == 2) {
                    v0 = v0 / (1.f + __expf(-v0));
                    v1 = v1 / (1.f + __expf(-v1));
                }
                if (OF)
                    *(float2*)&OF[(size_t)crow * N + col] = make_float2(v0, v1);
                else
                    OH[(size_t)crow * (N >> 1) + (col >> 1)] = packh2(v0, v1);
            }
        }
    }
}

// ========== fp16-split flash attention ==========
// smem u32 offsets (pads: Q/K/P rows 32+4=36; V rows 64+8=72)
#define QOFF 0
#define QLOFF 2304
#define KOFF 4608
#define KLOFF 6912
#define VOFF 9216
#define VLOFF 11520
#define POFF 13824
#define PLOFF 16128
#define ATTN_SMEM (18432 * 4)

__global__ void __launch_bounds__(256, 2)
attn_half_kernel(const uint32_t* __restrict__ Qh, const uint32_t* __restrict__ Ql,
                 const uint32_t* __restrict__ Kh, const uint32_t* __restrict__ Kl,
                 const uint32_t* __restrict__ Vh, const uint32_t* __restrict__ Vl,
                 uint32_t* __restrict__ Ch, uint32_t* __restrict__ Cl)
{
    extern __shared__ uint32_t smu[];
    __shared__ float redm[128], reds[128];

    int qt = blockIdx.x, h = blockIdx.y, b = blockIdx.z;
    int tid = threadIdx.x;
    int w = tid >> 5, lane = tid & 31;
    int wm = w & 3, wn = w >> 2;
    int g = lane >> 2, ct = lane & 3;
    int r0 = wm * 16 + g, r1 = r0 + 8;

    int qglob = b * SS + qt * 64;

    // load Q planes once
#pragma unroll
    for (int i = 0; i < 4; i++) {
        int c = tid + i * 256;
        int plane = c >> 9, cc = c & 511;
        int row = cc >> 3, seg = cc & 7;
        const uint32_t* src = plane ? Ql : Qh;
        uint32_t dst = smem_u32(smu + (plane ? QLOFF : QOFF));
        cp16(dst + (uint32_t)(row * 36 + seg * 4) * 4,
             src + (size_t)(qglob + row) * DP + h * 32 + seg * 4);
    }
    cp_commit();

    float oacc[4][4];
#pragma unroll
    for (int ni = 0; ni < 4; ni++)
#pragma unroll
        for (int j = 0; j < 4; j++) oacc[ni][j] = 0.f;
    float mrun0 = -1e30f, mrun1 = -1e30f, lrun0 = 0.f, lrun1 = 0.f;

    const uint32_t* Qhs = smu + QOFF;  const uint32_t* Qls = smu + QLOFF;
    const uint32_t* Khs = smu + KOFF;  const uint32_t* Kls = smu + KLOFF;
    const uint32_t* Vhs = smu + VOFF;  const uint32_t* Vls = smu + VLOFF;
    uint32_t* Phs = smu + POFF;        uint32_t* Pls = smu + PLOFF;

    for (int t = 0; t < SS / 64; t++) {
        int k0t = t * 64;
        __syncthreads();
        // K planes: 64 rows x 8 segs x 2 planes
#pragma unroll
        for (int i = 0; i < 4; i++) {
            int c = tid + i * 256;
            int plane = c >> 9, cc = c & 511;
            int row = cc >> 3, seg = cc & 7;
            const uint32_t* src = plane ? Kl : Kh;
            uint32_t dst = smem_u32(smu + (plane ? KLOFF : KOFF));
            cp16(dst + (uint32_t)(row * 36 + seg * 4) * 4,
                 src + (size_t)(b * SS + k0t + row) * DP + h * 32 + seg * 4);
        }
        // V planes: 32 pair-rows x 16 segs x 2 planes
#pragma unroll
        for (int i = 0; i < 4; i++) {
            int c = tid + i * 256;
            int plane = c >> 9, cc = c & 511;
            int row = cc >> 4, seg = cc & 15;
            const uint32_t* src = plane ? Vl : Vh;
            uint32_t dst = smem_u32(smu + (plane ? VLOFF : VOFF));
            cp16(dst + (uint32_t)(row * 72 + seg * 4) * 4,
                 src + (size_t)((b * SS + k0t) / 2 + row) * DD + h * 64 + seg * 4);
        }
        cp_commit();
        cp_wait0();
        __syncthreads();

        // ---- S = Q K^T (fp16 split) ----
        float sacc[4][4];
#pragma unroll
        for (int ni = 0; ni < 4; ni++)
#pragma unroll
            for (int j = 0; j < 4; j++) sacc[ni][j] = 0.f;
#pragma unroll
        for (int ks = 0; ks < 4; ks++) {
            int kb = ks * 8;
            uint32_t ah[4] = { Qhs[r0 * 36 + kb + ct], Qhs[r1 * 36 + kb + ct],
                               Qhs[r0 * 36 + kb + ct + 4], Qhs[r1 * 36 + kb + ct + 4] };
            uint32_t al[4] = { Qls[r0 * 36 + kb + ct], Qls[r1 * 36 + kb + ct],
                               Qls[r0 * 36 + kb + ct + 4], Qls[r1 * 36 + kb + ct + 4] };
#pragma unroll
            for (int ni = 0; ni < 4; ni++) {
                int n = wn * 32 + ni * 8 + g;
                uint32_t bh[2] = { Khs[n * 36 + kb + ct], Khs[n * 36 + kb + ct + 4] };
                uint32_t bl[2] = { Kls[n * 36 + kb + ct], Kls[n * 36 + kb + ct + 4] };
                mma_f16(sacc[ni], ah, bh);
                mma_f16(sacc[ni], ah, bl);
                mma_f16(sacc[ni], al, bh);
            }
        }
#pragma unroll
        for (int ni = 0; ni < 4; ni++)
#pragma unroll
            for (int j = 0; j < 4; j++) sacc[ni][j] *= 0.125f;

        // ---- online softmax ----
        float mx0 = -1e30f, mx1 = -1e30f;
#pragma unroll
        for (int ni = 0; ni < 4; ni++) {
            mx0 = fmaxf(mx0, fmaxf(sacc[ni][0], sacc[ni][1]));
            mx1 = fmaxf(mx1, fmaxf(sacc[ni][2], sacc[ni][3]));
        }
        mx0 = fmaxf(mx0, __shfl_xor_sync(~0u, mx0, 1));
        mx0 = fmaxf(mx0, __shfl_xor_sync(~0u, mx0, 2));
        mx1 = fmaxf(mx1, __shfl_xor_sync(~0u, mx1, 1));
        mx1 = fmaxf(mx1, __shfl_xor_sync(~0u, mx1, 2));
        if (ct == 0) { redm[wn * 64 + r0] = mx0; redm[wn * 64 + r1] = mx1; }
        __syncthreads();
        float mn0 = fmaxf(mrun0, fmaxf(redm[r0], redm[64 + r0]));
        float mn1 = fmaxf(mrun1, fmaxf(redm[r1], redm[64 + r1]));
        float c0 = fexp(mrun0 - mn0), c1 = fexp(mrun1 - mn1);
        mrun0 = mn0; mrun1 = mn1;
        float sum0 = 0.f, sum1 = 0.f;
#pragma unroll
        for (int ni = 0; ni < 4; ni++) {
            float p00 = fexp(sacc[ni][0] - mn0), p01 = fexp(sacc[ni][1] - mn0);
            float p10 = fexp(sacc[ni][2] - mn1), p11 = fexp(sacc[ni][3] - mn1);
            sum0 += p00 + p01; sum1 += p10 + p11;
            int pc = wn * 16 + ni * 4 + ct;
            uint32_t hh, ll;
            split2(p00, p01, hh, ll);
            Phs[r0 * 36 + pc] = hh; Pls[r0 * 36 + pc] = ll;
            split2(p10, p11, hh, ll);
            Phs[r1 * 36 + pc] = hh; Pls[r1 * 36 + pc] = ll;
        }
        sum0 += __shfl_xor_sync(~0u, sum0, 1);
        sum0 += __shfl_xor_sync(~0u, sum0, 2);
        sum1 += __shfl_xor_sync(~0u, sum1, 1);
        sum1 += __shfl_xor_sync(~0u, sum1, 2);
        if (ct == 0) { reds[wn * 64 + r0] = sum0; reds[wn * 64 + r1] = sum1; }
        __syncthreads();
        lrun0 = lrun0 * c0 + reds[r0] + reds[64 + r0];
        lrun1 = lrun1 * c1 + reds[r1] + reds[64 + r1];
#pragma unroll
        for (int ni = 0; ni < 4; ni++) {
            oacc[ni][0] *= c0; oacc[ni][1] *= c0;
            oacc[ni][2] *= c1; oacc[ni][3] *= c1;
        }

        // ---- O += P V (fp16 split) ----
#pragma unroll
        for (int ks = 0; ks < 4; ks++) {
            int kb = ks * 8;
            uint32_t ah[4] = { Phs[r0 * 36 + kb + ct], Phs[r1 * 36 + kb + ct],
                               Phs[r0 * 36 + kb + ct + 4], Phs[r1 * 36 + kb + ct + 4] };
            uint32_t al[4] = { Pls[r0 * 36 + kb + ct], Pls[r1 * 36 + kb + ct],
                               Pls[r0 * 36 + kb + ct + 4], Pls[r1 * 36 + kb + ct + 4] };
#pragma unroll
            for (int ni = 0; ni < 4; ni++) {
                int n = wn * 32 + ni * 8 + g;
                uint32_t bh[2] = { Vhs[(kb + ct) * 72 + n], Vhs[(kb + ct + 4) * 72 + n] };
                uint32_t bl[2] = { Vls[(kb + ct) * 72 + n], Vls[(kb + ct + 4) * 72 + n] };
                mma_f16(oacc[ni], ah, bh);
                mma_f16(oacc[ni], ah, bl);
                mma_f16(oacc[ni], al, bh);
            }
        }
    }

    float inv0 = 1.f / lrun0, inv1 = 1.f / lrun1;
#pragma unroll
    for (int ni = 0; ni < 4; ni++) {
        int pc = h * 32 + wn * 16 + ni * 4 + ct;
        uint32_t hh, ll;
        size_t o0 = (size_t)(qglob + r0) * DP + pc;
        split2(oacc[ni][0] * inv0, oacc[ni][1] * inv0, hh, ll);
        Ch[o0] = hh; Cl[o0] = ll;
        size_t o1 = (size_t)(qglob + r1) * DP + pc;
        split2(oacc[ni][2] * inv1, oacc[ni][3] * inv1, hh, ll);
        Ch[o1] = hh; Cl[o1] = ll;
    }
}

// ---------------- layernorm (writes fp32 + packed fp16) ----------------
__global__ void ln_kernel(const float* __restrict__ in,
                          const float* __restrict__ gam,
                          const float* __restrict__ bet,
                          float* __restrict__ out, uint32_t* __restrict__ outh)
{
    __shared__ float ssum[8], ssum2[8];
    __shared__ float smean, srstd;
    int t = blockIdx.x;
    const float4* r = (const float4*)(in + (size_t)t * DD);
    float4 vv = r[threadIdx.x];
    float s = vv.x + vv.y + vv.z + vv.w;
    float s2 = vv.x * vv.x + vv.y * vv.y + vv.z * vv.z + vv.w * vv.w;
    int lane = threadIdx.x & 31, w = threadIdx.x >> 5;
#pragma unroll
    for (int o = 16; o; o >>= 1) {
        s += __shfl_xor_sync(~0u, s, o);
        s2 += __shfl_xor_sync(~0u, s2, o);
    }
    if (!lane) { ssum[w] = s; ssum2[w] = s2; }
    __syncthreads();
    if (threadIdx.x == 0) {
        float a = 0.f, bb = 0.f;
#pragma unroll
        for (int i = 0; i < 8; i++) { a += ssum[i]; bb += ssum2[i]; }
        float mean = a * (1.f / DD);
        float var = bb * (1.f / DD) - mean * mean;
        smean = mean; srstd = rsqrtf(var + 1e-5f);
    }
    __syncthreads();
    float4 g4 = ((const float4*)gam)[threadIdx.x];
    float4 b4 = ((const float4*)bet)[threadIdx.x];
    float m = smean, rs = srstd;
    float4 o4;
    o4.x = (vv.x - m) * rs * g4.x + b4.x;
    o4.y = (vv.y - m) * rs * g4.y + b4.y;
    o4.z = (vv.z - m) * rs * g4.z + b4.z;
    o4.w = (vv.w - m) * rs * g4.w + b4.w;
    ((float4*)(out + (size_t)t * DD))[threadIdx.x] = o4;
    if (outh) {
        outh[(size_t)t * DP + threadIdx.x * 2] = packh2(o4.x, o4.y);
        outh[(size_t)t * DP + threadIdx.x * 2 + 1] = packh2(o4.z, o4.w);
    }
}

// ---------------- gate ----------------
__global__ void zero_counts_kernel() {
    if (threadIdx.x < EE) g_counts[threadIdx.x] = 0;
}

__global__ void gate_kernel(const float* __restrict__ x1,
                            const float* __restrict__ gw,
                            const float* __restrict__ gb)
{
    int t = blockIdx.x * (blockDim.x / 32) + (threadIdx.x >> 5);
    int lane = threadIdx.x & 31;
    float acc[EE] = {};
    const float* xr = x1 + (size_t)t * DD;
    for (int d = lane; d < DD; d += 32) {
        float xv = xr[d];
        const float* grow = gw + (size_t)d * EE;
#pragma unroll
        for (int e = 0; e < EE; e++) acc[e] += xv * grow[e];
    }
#pragma unroll
    for (int e = 0; e < EE; e++)
#pragma unroll
        for (int o = 16; o; o >>= 1) acc[e] += __shfl_xor_sync(~0u, acc[e], o);
    if (lane == 0) {
#pragma unroll
        for (int e = 0; e < EE; e++) acc[e] += gb[e];
        float best = -1e30f; int bi = 0;
#pragma unroll
        for (int e = 0; e < EE; e++)
            if (acc[e] > best) { best = acc[e]; bi = e; }
        float best2 = -1e30f; int bi2 = 0;
#pragma unroll
        for (int e = 0; e < EE; e++)
            if (e != bi && acc[e] > best2) { best2 = acc[e]; bi2 = e; }
        float w0 = 1.f / (1.f + __expf(best2 - best));
        g_gatew[2 * t] = w0;
        g_gatew[2 * t + 1] = 1.f - w0;
        int p0 = atomicAdd(&g_counts[bi], 1);
        g_list[bi * TT + p0] = 2 * t;
        int p1 = atomicAdd(&g_counts[bi2], 1);
        g_list[bi2 * TT + p1] = 2 * t + 1;
    }
}

// ---------------- combine + residual + LN3 ----------------
__global__ void combine_ln_kernel(const float* __restrict__ x1,
                                  const float* __restrict__ gam,
                                  const float* __restrict__ bet,
                                  float* __restrict__ out)
{
    __shared__ float ssum[8], ssum2[8];
    __shared__ float smean, srstd;
    int t = blockIdx.x;
    float w0 = g_gatew[2 * t], w1 = g_gatew[2 * t + 1];
    const float4* xr = (const float4*)(x1 + (size_t)t * DD);
    const float4* y0 = (const float4*)(g_y + (size_t)(2 * t) * DD);
    const float4* y1 = (const float4*)(g_y + (size_t)(2 * t + 1) * DD);
    float4 a = xr[threadIdx.x];
    float4 c0 = y0[threadIdx.x];
    float4 c1 = y1[threadIdx.x];
    float4 vv;
    vv.x = a.x + w0 * c0.x + w1 * c1.x;
    vv.y = a.y + w0 * c0.y + w1 * c1.y;
    vv.z = a.z + w0 * c0.z + w1 * c1.z;
    vv.w = a.w + w0 * c0.w + w1 * c1.w;
    float s = vv.x + vv.y + vv.z + vv.w;
    float s2 = vv.x * vv.x + vv.y * vv.y + vv.z * vv.z + vv.w * vv.w;
    int lane = threadIdx.x & 31, w = threadIdx.x >> 5;
#pragma unroll
    for (int o = 16; o; o >>= 1) {
        s += __shfl_xor_sync(~0u, s, o);
        s2 += __shfl_xor_sync(~0u, s2, o);
    }
    if (!lane) { ssum[w] = s; ssum2[w] = s2; }
    __syncthreads();
    if (threadIdx.x == 0) {
        float aa = 0.f, bb = 0.f;
#pragma unroll
        for (int i = 0; i < 8; i++) { aa += ssum[i]; bb += ssum2[i]; }
        float mean = aa * (1.f / DD);
        float var = bb * (1.f / DD) - mean * mean;
        smean = mean; srstd = rsqrtf(var + 1e-5f);
    }
    __syncthreads();
    float4 g4 = ((const float4*)gam)[threadIdx.x];
    float4 b4 = ((const float4*)bet)[threadIdx.x];
    float m = smean, rs = srstd;
    float4 o4;
    o4.x = (vv.x - m) * rs * g4.x + b4.x;
    o4.y = (vv.y - m) * rs * g4.y + b4.y;
    o4.z = (vv.z - m) * rs * g4.z + b4.z;
    o4.w = (vv.w - m) * rs * g4.w + b4.w;
    ((float4*)(out + (size_t)t * DD))[threadIdx.x] = o4;
}

// ---------------- launch ----------------
extern "C" void kernel_launch(void* const* d_in, const int* in_sizes, int n_in,
                              void* d_out, int out_size)
{
    const float* x    = (const float*)d_in[0];
    const float* Wq   = (const float*)d_in[1];
    const float* bq   = (const float*)d_in[2];
    const float* Wk   = (const float*)d_in[3];
    const float* bk   = (const float*)d_in[4];
    const float* Wv   = (const float*)d_in[5];
    const float* bv   = (const float*)d_in[6];
    const float* Wo   = (const float*)d_in[7];
    const float* bo   = (const float*)d_in[8];
    const float* ln1g = (const float*)d_in[9];
    const float* ln1b = (const float*)d_in[10];
    const float* gw   = (const float*)d_in[11];
    const float* gb   = (const float*)d_in[12];
    const float* W1   = (const float*)d_in[13];
    const float* b1   = (const float*)d_in[14];
    const float* W2   = (const float*)d_in[15];
    const float* b2   = (const float*)d_in[16];
    const float* ln3g = (const float*)d_in[17];
    const float* ln3b = (const float*)d_in[18];
    float* out = (float*)d_out;

    static int attr_set = 0;
    if (!attr_set) {
        cudaFuncSetAttribute(mm_half_split, cudaFuncAttributeMaxDynamicSharedMemorySize, SPLIT_SMEM);
        cudaFuncSetAttribute(mm_half_plain, cudaFuncAttributeMaxDynamicSharedMemorySize, PLAIN_SMEM);
        cudaFuncSetAttribute(attn_half_kernel, cudaFuncAttributeMaxDynamicSharedMemorySize, ATTN_SMEM);
        attr_set = 1;
    }

    uint32_t *pxh, *pxl, *pwqkvh, *pwqkvl, *pwoh, *pwol, *pqkh, *pqkl;
    uint32_t *pvh, *pvl, *pcth, *pctl, *px1h, *pw1h, *pw2h, *pacth;
    float *pv, *pres1, *px1, *py, *pbqkv;
    int *pcounts, *plist;
    cudaGetSymbolAddress((void**)&pxh, g_xh);
    cudaGetSymbolAddress((void**)&pxl, g_xl);
    cudaGetSymbolAddress((void**)&pwqkvh, g_wqkvh);
    cudaGetSymbolAddress((void**)&pwqkvl, g_wqkvl);
    cudaGetSymbolAddress((void**)&pwoh, g_woh);
    cudaGetSymbolAddress((void**)&pwol, g_wol);
    cudaGetSymbolAddress((void**)&pqkh, g_qkh);
    cudaGetSymbolAddress((void**)&pqkl, g_qkl);
    cudaGetSymbolAddress((void**)&pv, g_v);
    cudaGetSymbolAddress((void**)&pvh, g_vh);
    cudaGetSymbolAddress((void**)&pvl, g_vl);
    cudaGetSymbolAddress((void**)&pcth, g_cth);
    cudaGetSymbolAddress((void**)&pctl, g_ctl);
    cudaGetSymbolAddress((void**)&pres1, g_res1);
    cudaGetSymbolAddress((void**)&px1, g_x1);
    cudaGetSymbolAddress((void**)&px1h, g_x1h);
    cudaGetSymbolAddress((void**)&pw1h, g_w1h);
    cudaGetSymbolAddress((void**)&pw2h, g_w2h);
    cudaGetSymbolAddress((void**)&pacth, g_acth);
    cudaGetSymbolAddress((void**)&py, g_y);
    cudaGetSymbolAddress((void**)&pbqkv, g_bqkv);
    cudaGetSymbolAddress((void**)&pcounts, g_counts);
    cudaGetSymbolAddress((void**)&plist, g_list);

    // ---- packs ----
    pack_cols_kernel<<<TT, 256>>>(x, pxh, pxl);                                   // x
    pack_rows_kernel<<<dim3(1, DP), 256>>>(Wq, pwqkvh, pwqkvl, DD);
    pack_rows_kernel<<<dim3(1, DP), 256>>>(Wk, pwqkvh + DP * DD, pwqkvl + DP * DD, DD);
    pack_rows_kernel<<<dim3(1, DP), 256>>>(Wv, pwqkvh + 2 * DP * DD, pwqkvl + 2 * DP * DD, DD);
    pack_rows_kernel<<<dim3(1, DP), 256>>>(Wo, pwoh, pwol, DD);
    pack_rows_kernel<<<dim3(FF / 1024, EE * DP), 256>>>(W1, pw1h, nullptr, FF);   // plain
    pack_rows_kernel<<<dim3(1, EE * FF / 2), 256>>>(W2, pw2h, nullptr, DD);       // plain
    concat_bias_kernel<<<4, 256>>>(bq, bk, bv, pbqkv);

    // ---- QKV (split fp16): z0->Q packed, z1->K packed, z2->V fp32 ----
    mm_half_split<<<dim3(DD / 128, TT / 128, 3), 256, SPLIT_SMEM>>>(
        pxh, pxl, pwqkvh, pwqkvl, pbqkv, nullptr, pqkh, pqkl, pv, DD, DD, 2);

    // pack V along tokens
    pack_rows_kernel<<<dim3(1, TT / 2), 256>>>(pv, pvh, pvl, DD);

    // ---- attention ----
    attn_half_kernel<<<dim3(SS / 64, HH, 2), 256, ATTN_SMEM>>>(
        pqkh, pqkl, pqkh + (size_t)TT * DP, pqkl + (size_t)TT * DP,
        pvh, pvl, pcth, pctl);

    // ---- O projection + residual -> res1 (fp32) ----
    mm_half_split<<<dim3(DD / 128, TT / 128, 1), 256, SPLIT_SMEM>>>(
        pcth, pctl, pwoh, pwol, bo, x, nullptr, nullptr, pres1, DD, DD, 0);

    // LN1 (fp32 + fp16 pack)
    ln_kernel<<<TT, 256>>>(pres1, ln1g, ln1b, px1, px1h);

    // gate + dispatch
    zero_counts_kernel<<<1, 32>>>();
    gate_kernel<<<TT / 8, 256>>>(px1, gw, gb);

    // FFN1 (plain fp16, gathered) -> act packed
    mm_half_plain<<<dim3(FF / 128, TT / 128, EE), 256, PLAIN_SMEM>>>(
        px1h, pw1h, b1, pacth, nullptr, DD, FF, plist, pcounts, 1, 3);

    // FFN2 (plain fp16, gathered) -> y fp32
    mm_half_plain<<<dim3(DD / 128, TT / 128, EE), 256, PLAIN_SMEM>>>(
        pacth, pw2h, b2, nullptr, py, FF, DD, plist, pcounts, 0, 0);

    // combine + residual + LN3
    combine_ln_kernel<<<TT, 256>>>(px1, ln3g, ln3b, out);
}